// round 7
// baseline (speedup 1.0000x reference)
#include <cuda_runtime.h>
#include <cuda_bf16.h>
#include <cuda_fp16.h>
#include <math.h>
#include <stdint.h>

// Problem constants
#define Nn   8192
#define Ee   32768
#define DINc 1024
#define DHc  256
#define HHc  8
#define LLc  3
#define HDc  2048   // H*DH
#define NTc  5
#define N2c  4096   // merged Wl|Wr output width
#define CHc  64     // edge chunk capacity

// ---------------- device scratch ----------------
__device__ __half g_xlr[(size_t)Nn * N2c];         // merged xl|xr, fp16 (L2-resident)
__device__ float g_table[LLc * NTc * HDc];
__device__ int   g_deg[Nn];
__device__ int   g_hist[Nn * NTc];
__device__ int   g_rowptr[Nn + 1];
__device__ int   g_woff[Nn];
__device__ int   g_eid[Ee];

__device__ __nv_bfloat16 g_Apack[(size_t)Nn * 3 * DINc];
__device__ __nv_bfloat16 g_hpack[(size_t)Nn * 3 * DHc];
__device__ __nv_bfloat16 g_Bpack[10420224];

#define OFF_WIN  0
#define SZ_WIN   (DHc * 3 * DINc)
#define SZ_L     ((size_t)N2c * 3 * DHc)
#define OFF_WLR(l) (SZ_WIN + (size_t)(l) * SZ_L)
#define OFF_WOUT (SZ_WIN + (size_t)3 * SZ_L)

// ---------------- PTX helpers ----------------
__device__ __forceinline__ uint32_t smem_u32(const void* p) {
    uint32_t a;
    asm("{ .reg .u64 t; cvta.to.shared.u64 t, %1; cvt.u32.u64 %0, t; }" : "=r"(a) : "l"(p));
    return a;
}
__device__ __forceinline__ void cp16(uint32_t d, const void* g) {
    asm volatile("cp.async.cg.shared.global [%0], [%1], 16;" :: "r"(d), "l"(g));
}
__device__ __forceinline__ void ldsm_x4(uint32_t* r, uint32_t addr) {
    asm volatile("ldmatrix.sync.aligned.m8n8.x4.shared.b16 {%0,%1,%2,%3}, [%4];"
                 : "=r"(r[0]), "=r"(r[1]), "=r"(r[2]), "=r"(r[3]) : "r"(addr));
}
__device__ __forceinline__ void mma_bf16(float* c, const uint32_t* a, uint32_t b0, uint32_t b1) {
    asm volatile(
        "mma.sync.aligned.m16n8k16.row.col.f32.bf16.bf16.f32 "
        "{%0,%1,%2,%3}, {%4,%5,%6,%7}, {%8,%9}, {%0,%1,%2,%3};"
        : "+f"(c[0]), "+f"(c[1]), "+f"(c[2]), "+f"(c[3])
        : "r"(a[0]), "r"(a[1]), "r"(a[2]), "r"(a[3]), "r"(b0), "r"(b1));
}

// ---------------- CSR build ----------------
__global__ void k_zero() {
    int i = blockIdx.x * 256 + threadIdx.x;
    if (i < Nn) g_deg[i] = 0;
    if (i < Nn * NTc) g_hist[i] = 0;
}
__global__ void k_count(const int* __restrict__ ei, const int* __restrict__ ea) {
    int e = blockIdx.x * 256 + threadIdx.x;
    if (e < Ee) {
        int dst = ei[Ee + e];
        atomicAdd(&g_deg[dst], 1);
        atomicAdd(&g_hist[dst * NTc + ea[e]], 1);
    }
}
__global__ void k_scan() {
    __shared__ int part[256];
    int tid = threadIdx.x;
    int base = tid * 32;
    int s = 0;
    for (int i = 0; i < 32; ++i) s += g_deg[base + i];
    part[tid] = s;
    __syncthreads();
    for (int off = 1; off < 256; off <<= 1) {
        int v = (tid >= off) ? part[tid - off] : 0;
        __syncthreads();
        part[tid] += v;
        __syncthreads();
    }
    int run = (tid == 0) ? 0 : part[tid - 1];
    for (int i = 0; i < 32; ++i) {
        int n = base + i;
        g_rowptr[n] = run;
        g_woff[n] = run;
        run += g_deg[n];
    }
    if (tid == 255) g_rowptr[Nn] = run;
}
__global__ void k_fill(const int* __restrict__ ei) {
    int e = blockIdx.x * 256 + threadIdx.x;
    if (e < Ee) {
        int dst = ei[Ee + e];
        int pos = atomicAdd(&g_woff[dst], 1);
        g_eid[pos] = e;
    }
}
__global__ void k_sort() {
    int n = blockIdx.x * 256 + threadIdx.x;
    if (n < Nn) {
        int r0 = g_rowptr[n], r1 = g_rowptr[n + 1];
        for (int i = r0 + 1; i < r1; ++i) {
            int v = g_eid[i];
            int j = i - 1;
            while (j >= r0 && g_eid[j] > v) { g_eid[j + 1] = g_eid[j]; --j; }
            g_eid[j + 1] = v;
        }
    }
}

// ---------------- fused packing: x, all weights, all tables ----------------
__global__ void __launch_bounds__(256)
k_pack_all(const float* __restrict__ x,
           const float* __restrict__ W_in,
           const float* __restrict__ Wl, const float* __restrict__ Wr,
           const float* __restrict__ W_out,
           const float* __restrict__ edge_emb, const float* __restrict__ We,
           __nv_bfloat16* __restrict__ Apk, __nv_bfloat16* __restrict__ Bpk) {
    const int bid = blockIdx.x;
    const int tid = threadIdx.x;

    if (bid < Nn) {
        const float4 v = *reinterpret_cast<const float4*>(x + (size_t)bid * DINc + tid * 4);
        __nv_bfloat16 h0 = __float2bfloat16(v.x), h1 = __float2bfloat16(v.y);
        __nv_bfloat16 h2 = __float2bfloat16(v.z), h3 = __float2bfloat16(v.w);
        __nv_bfloat162 hp0 = {h0, h1}, hp1 = {h2, h3};
        __nv_bfloat162 lp0 = {__float2bfloat16(v.x - __bfloat162float(h0)),
                              __float2bfloat16(v.y - __bfloat162float(h1))};
        __nv_bfloat162 lp1 = {__float2bfloat16(v.z - __bfloat162float(h2)),
                              __float2bfloat16(v.w - __bfloat162float(h3))};
        __nv_bfloat16* p = Apk + (size_t)bid * 3 * DINc + tid * 4;
        reinterpret_cast<__nv_bfloat162*>(p)[0] = hp0;
        reinterpret_cast<__nv_bfloat162*>(p)[1] = hp1;
        reinterpret_cast<__nv_bfloat162*>(p + DINc)[0] = lp0;
        reinterpret_cast<__nv_bfloat162*>(p + DINc)[1] = lp1;
        reinterpret_cast<__nv_bfloat162*>(p + 2 * DINc)[0] = hp0;
        reinterpret_cast<__nv_bfloat162*>(p + 2 * DINc)[1] = hp1;
        return;
    }
    if (bid < Nn + 256 + 3072 + 64) {
        const float* W; __nv_bfloat16* P; int K, N, nb, kb;
        int id = bid - Nn;
        if (id < 256) {
            W = W_in; P = Bpk + OFF_WIN; K = DINc; N = DHc;
            nb = id & 7; kb = id >> 3;
        } else if (id < 256 + 3072) {
            int id2 = id - 256;
            int mat = id2 >> 9;
            int t = id2 & 511;
            int l = mat >> 1, side = mat & 1;
            W = (side == 0 ? Wl : Wr) + (size_t)l * DHc * HDc;
            P = Bpk + OFF_WLR(l) + (size_t)side * HDc * 3 * DHc;
            K = DHc; N = HDc;
            nb = t & 63; kb = t >> 6;
        } else {
            int id2 = id - 256 - 3072;
            W = W_out; P = Bpk + OFF_WOUT; K = DHc; N = DHc;
            nb = id2 & 7; kb = id2 >> 3;
        }
        __shared__ float tbuf[32][33];
        int tx = tid & 31, ty = tid >> 5;
        #pragma unroll
        for (int i = 0; i < 32; i += 8)
            tbuf[ty + i][tx] = W[(size_t)(kb * 32 + ty + i) * N + nb * 32 + tx];
        __syncthreads();
        int K3 = 3 * K;
        #pragma unroll
        for (int i = 0; i < 32; i += 8) {
            int n = nb * 32 + ty + i;
            int k = kb * 32 + tx;
            float v = tbuf[tx][ty + i];
            __nv_bfloat16 hi = __float2bfloat16(v);
            __nv_bfloat16 lo = __float2bfloat16(v - __bfloat162float(hi));
            P[(size_t)n * K3 + k]         = hi;
            P[(size_t)n * K3 + K + k]     = hi;
            P[(size_t)n * K3 + 2 * K + k] = lo;
        }
        return;
    }
    {
        int id = bid - (Nn + 256 + 3072 + 64);
        int lt = id >> 3;
        int jb = id & 7;
        int l = lt / NTc, t = lt % NTc;
        int j = jb * 256 + tid;
        const float* w = We + (size_t)l * DHc * HDc + j;
        const float* e = edge_emb + t * DHc;
        float s = 0.f;
        #pragma unroll 4
        for (int k = 0; k < DHc; ++k) s = fmaf(e[k], w[(size_t)k * HDc], s);
        g_table[(size_t)l * NTc * HDc + t * HDc + j] = s;
    }
}

// ---------------- GEMM kernel 1 (proj): CTA 128x128, warp 32x64, 3-stage, 2 CTA/SM ----
#define GSTAGE 3
#define STG_BYTES 32768
#define GEMM_SMEM (GSTAGE * STG_BYTES)

__global__ void __launch_bounds__(256, 2)
k_gemm_mma(const __nv_bfloat16* __restrict__ A, const __nv_bfloat16* __restrict__ B,
           const float* __restrict__ bias, float* __restrict__ C, int Ktot, int Nc,
           const float* __restrict__ emb, const int* __restrict__ types,
           __nv_bfloat16* __restrict__ packA) {
    extern __shared__ __align__(1024) char smem[];
    const uint32_t sb = smem_u32(smem);
    const int tid = threadIdx.x;
    const int lane = tid & 31, w = tid >> 5;
    const int wm = w & 3, wn = w >> 2;
    const int row0 = blockIdx.y * 128;
    const int col0 = blockIdx.x * 128;
    const int nch = Ktot >> 6;

    float acc[2][8][4];
    #pragma unroll
    for (int i = 0; i < 2; ++i)
        #pragma unroll
        for (int j = 0; j < 8; ++j)
            #pragma unroll
            for (int q = 0; q < 4; ++q) acc[i][j][q] = 0.f;

    uint32_t sm_off[4];
    const __nv_bfloat16* gA[4];
    const __nv_bfloat16* gB[4];
    #pragma unroll
    for (int u = 0; u < 4; ++u) {
        int i = tid + u * 256;
        int r = i >> 3, seg = i & 7;
        uint32_t off = (uint32_t)(r * 128 + seg * 16);
        sm_off[u] = off ^ ((off >> 3) & 0x70);
        gA[u] = A + (size_t)(row0 + r) * Ktot + (seg << 3);
        gB[u] = B + (size_t)(col0 + r) * Ktot + (seg << 3);
    }
    auto load_chunk = [&](int c) {
        const uint32_t s = sb + (uint32_t)((c % GSTAGE) * STG_BYTES);
        const int kof = c << 6;
        #pragma unroll
        for (int u = 0; u < 4; ++u) cp16(s + sm_off[u], gA[u] + kof);
        #pragma unroll
        for (int u = 0; u < 4; ++u) cp16(s + 16384 + sm_off[u], gB[u] + kof);
        asm volatile("cp.async.commit_group;");
    };
    #pragma unroll
    for (int c = 0; c < GSTAGE - 1; ++c) load_chunk(c);

    uint32_t a_base[2], a_swz[2];
    #pragma unroll
    for (int mb = 0; mb < 2; ++mb) {
        int row = wm * 32 + mb * 16 + (lane & 15);
        a_base[mb] = (uint32_t)(row * 128 + ((lane >> 4) << 4));
        a_swz[mb] = (uint32_t)((row & 7) << 4);
    }
    uint32_t b_base[4], b_swz[4];
    #pragma unroll
    for (int nb = 0; nb < 4; ++nb) {
        int row = wn * 64 + nb * 16 + (lane & 7) + ((lane >> 4) << 3);
        b_base[nb] = (uint32_t)(row * 128 + (((lane >> 3) & 1) << 4));
        b_swz[nb] = (uint32_t)((row & 7) << 4);
    }

    for (int c = 0; c < nch; ++c) {
        asm volatile("cp.async.wait_group %0;" :: "n"(GSTAGE - 2));
        __syncthreads();
        if (c + GSTAGE - 1 < nch) load_chunk(c + GSTAGE - 1);
        else asm volatile("cp.async.commit_group;");
        const uint32_t stb = sb + (uint32_t)((c % GSTAGE) * STG_BYTES);
        #pragma unroll
        for (int kk = 0; kk < 4; ++kk) {
            const uint32_t kby = (uint32_t)(kk * 32);
            uint32_t a[2][4];
            #pragma unroll
            for (int mb = 0; mb < 2; ++mb)
                ldsm_x4(a[mb], stb + ((a_base[mb] + kby) ^ a_swz[mb]));
            uint32_t b[4][4];
            #pragma unroll
            for (int nb = 0; nb < 4; ++nb)
                ldsm_x4(b[nb], stb + 16384 + ((b_base[nb] + kby) ^ b_swz[nb]));
            #pragma unroll
            for (int mb = 0; mb < 2; ++mb)
                #pragma unroll
                for (int nb = 0; nb < 4; ++nb) {
                    mma_bf16(acc[mb][2 * nb],     a[mb], b[nb][0], b[nb][1]);
                    mma_bf16(acc[mb][2 * nb + 1], a[mb], b[nb][2], b[nb][3]);
                }
        }
    }

    const int r_base = row0 + wm * 32 + (lane >> 2);
    const int c_base = col0 + wn * 64 + ((lane & 3) << 1);
    const int K3 = 3 * Nc;
    #pragma unroll
    for (int mb = 0; mb < 2; ++mb) {
        const int r1 = r_base + mb * 16;
        const int r2 = r1 + 8;
        #pragma unroll
        for (int nt = 0; nt < 8; ++nt) {
            const int col = c_base + nt * 8;
            float bx = bias[col], by = bias[col + 1];
            float e1x = 0.f, e1y = 0.f, e2x = 0.f, e2y = 0.f;
            if (emb) {
                const float* em1 = emb + (size_t)types[r1] * Nc + col;
                const float* em2 = emb + (size_t)types[r2] * Nc + col;
                e1x = em1[0]; e1y = em1[1]; e2x = em2[0]; e2y = em2[1];
            }
            float v00 = acc[mb][nt][0] + bx + e1x;
            float v01 = acc[mb][nt][1] + by + e1y;
            float v10 = acc[mb][nt][2] + bx + e2x;
            float v11 = acc[mb][nt][3] + by + e2y;
            if (C) {
                float2 t0 = {v00, v01}, t1 = {v10, v11};
                *reinterpret_cast<float2*>(&C[(size_t)r1 * Nc + col]) = t0;
                *reinterpret_cast<float2*>(&C[(size_t)r2 * Nc + col]) = t1;
            }
            if (packA) {
                __nv_bfloat16 h00 = __float2bfloat16(v00);
                __nv_bfloat16 h01 = __float2bfloat16(v01);
                __nv_bfloat16 h10 = __float2bfloat16(v10);
                __nv_bfloat16 h11 = __float2bfloat16(v11);
                __nv_bfloat162 hp1 = {h00, h01};
                __nv_bfloat162 hp2 = {h10, h11};
                __nv_bfloat162 lp1 = {__float2bfloat16(v00 - __bfloat162float(h00)),
                                      __float2bfloat16(v01 - __bfloat162float(h01))};
                __nv_bfloat162 lp2 = {__float2bfloat16(v10 - __bfloat162float(h10)),
                                      __float2bfloat16(v11 - __bfloat162float(h11))};
                __nv_bfloat16* p1 = packA + (size_t)r1 * K3 + col;
                __nv_bfloat16* p2 = packA + (size_t)r2 * K3 + col;
                *reinterpret_cast<__nv_bfloat162*>(p1)          = hp1;
                *reinterpret_cast<__nv_bfloat162*>(p1 + Nc)     = lp1;
                *reinterpret_cast<__nv_bfloat162*>(p1 + 2 * Nc) = hp1;
                *reinterpret_cast<__nv_bfloat162*>(p2)          = hp2;
                *reinterpret_cast<__nv_bfloat162*>(p2 + Nc)     = lp2;
                *reinterpret_cast<__nv_bfloat162*>(p2 + 2 * Nc) = hp2;
            }
        }
    }
}

// ---------------- GEMM kernel 2 (merged xl|xr): CTA 128x256, warp 64x64, 4-stage ----
#define BGSTAGE 4
#define BSTG_BYTES 49152
#define BGEMM_SMEM (BGSTAGE * BSTG_BYTES)

__global__ void __launch_bounds__(256, 1)
k_gemm_big(const __nv_bfloat16* __restrict__ A, const __nv_bfloat16* __restrict__ B,
           const float* __restrict__ bias, const float* __restrict__ bias2, int halfN,
           __half* __restrict__ C, int Ktot, int Nc) {
    extern __shared__ __align__(1024) char smem[];
    const uint32_t sb = smem_u32(smem);
    const int tid = threadIdx.x;
    const int lane = tid & 31, w = tid >> 5;
    const int wm = w & 1, wn = w >> 1;
    const int row0 = blockIdx.y * 128;
    const int col0 = blockIdx.x * 256;
    const int nch = Ktot >> 6;

    float acc[4][8][4];
    #pragma unroll
    for (int i = 0; i < 4; ++i)
        #pragma unroll
        for (int j = 0; j < 8; ++j)
            #pragma unroll
            for (int q = 0; q < 4; ++q) acc[i][j][q] = 0.f;

    uint32_t sm_offA[4], sm_offB[8];
    const __nv_bfloat16* gA[4];
    const __nv_bfloat16* gB[8];
    #pragma unroll
    for (int u = 0; u < 4; ++u) {
        int i = tid + u * 256;
        int r = i >> 3, seg = i & 7;
        uint32_t off = (uint32_t)(r * 128 + seg * 16);
        sm_offA[u] = off ^ ((off >> 3) & 0x70);
        gA[u] = A + (size_t)(row0 + r) * Ktot + (seg << 3);
    }
    #pragma unroll
    for (int u = 0; u < 8; ++u) {
        int i = tid + u * 256;
        int r = i >> 3, seg = i & 7;
        uint32_t off = (uint32_t)(r * 128 + seg * 16);
        sm_offB[u] = off ^ ((off >> 3) & 0x70);
        gB[u] = B + (size_t)(col0 + r) * Ktot + (seg << 3);
    }
    auto load_chunk = [&](int c) {
        const uint32_t s = sb + (uint32_t)((c % BGSTAGE) * BSTG_BYTES);
        const int kof = c << 6;
        #pragma unroll
        for (int u = 0; u < 4; ++u) cp16(s + sm_offA[u], gA[u] + kof);
        #pragma unroll
        for (int u = 0; u < 8; ++u) cp16(s + 16384 + sm_offB[u], gB[u] + kof);
        asm volatile("cp.async.commit_group;");
    };
    #pragma unroll
    for (int c = 0; c < BGSTAGE - 1; ++c) load_chunk(c);

    uint32_t a_base[4], a_swz[4];
    #pragma unroll
    for (int mb = 0; mb < 4; ++mb) {
        int row = wm * 64 + mb * 16 + (lane & 15);
        a_base[mb] = (uint32_t)(row * 128 + ((lane >> 4) << 4));
        a_swz[mb] = (uint32_t)((row & 7) << 4);
    }
    uint32_t b_base[4], b_swz[4];
    #pragma unroll
    for (int nb = 0; nb < 4; ++nb) {
        int row = wn * 64 + nb * 16 + (lane & 7) + ((lane >> 4) << 3);
        b_base[nb] = (uint32_t)(row * 128 + (((lane >> 3) & 1) << 4));
        b_swz[nb] = (uint32_t)((row & 7) << 4);
    }

    for (int c = 0; c < nch; ++c) {
        asm volatile("cp.async.wait_group %0;" :: "n"(BGSTAGE - 2));
        __syncthreads();
        if (c + BGSTAGE - 1 < nch) load_chunk(c + BGSTAGE - 1);
        else asm volatile("cp.async.commit_group;");
        const uint32_t stb = sb + (uint32_t)((c % BGSTAGE) * BSTG_BYTES);
        #pragma unroll
        for (int kk = 0; kk < 4; ++kk) {
            const uint32_t kby = (uint32_t)(kk * 32);
            uint32_t a[4][4];
            #pragma unroll
            for (int mb = 0; mb < 4; ++mb)
                ldsm_x4(a[mb], stb + ((a_base[mb] + kby) ^ a_swz[mb]));
            uint32_t b[4][4];
            #pragma unroll
            for (int nb = 0; nb < 4; ++nb)
                ldsm_x4(b[nb], stb + 16384 + ((b_base[nb] + kby) ^ b_swz[nb]));
            #pragma unroll
            for (int mb = 0; mb < 4; ++mb)
                #pragma unroll
                for (int nb = 0; nb < 4; ++nb) {
                    mma_bf16(acc[mb][2 * nb],     a[mb], b[nb][0], b[nb][1]);
                    mma_bf16(acc[mb][2 * nb + 1], a[mb], b[nb][2], b[nb][3]);
                }
        }
    }

    const float* bp = bias;
    int cadj = 0;
    if (bias2 && col0 >= halfN) { bp = bias2; cadj = halfN; }
    const int r_base = row0 + wm * 64 + (lane >> 2);
    const int c_base = col0 + wn * 64 + ((lane & 3) << 1);
    #pragma unroll
    for (int mb = 0; mb < 4; ++mb) {
        const int r1 = r_base + mb * 16;
        const int r2 = r1 + 8;
        #pragma unroll
        for (int nt = 0; nt < 8; ++nt) {
            const int col = c_base + nt * 8;
            float bx = bp[col - cadj], by = bp[col + 1 - cadj];
            __half2 t0 = __floats2half2_rn(acc[mb][nt][0] + bx, acc[mb][nt][1] + by);
            __half2 t1 = __floats2half2_rn(acc[mb][nt][2] + bx, acc[mb][nt][3] + by);
            *reinterpret_cast<__half2*>(&C[(size_t)r1 * Nc + col]) = t0;
            *reinterpret_cast<__half2*>(&C[(size_t)r2 * Nc + col]) = t1;
        }
    }
}

// ---------------- fused GATv2 edge kernel: 3-phase chunked softmax ----------------
__global__ void __launch_bounds__(256)
k_edge(const int* __restrict__ edge_index, const int* __restrict__ edge_attr,
       const float* __restrict__ att_l, const float* __restrict__ bgat_l,
       int loff, __nv_bfloat16* __restrict__ packH) {
    const int n = blockIdx.x;
    const int tid = threadIdx.x;
    const int lane = tid & 31;
    const int w = tid >> 5;                 // warp == head
    const int base = (w << 8) + (lane << 3);

    __shared__ float s_xr[HDc];
    __shared__ float s_att[HDc];
    __shared__ float s_lee[HDc];
    __shared__ float s_out[HDc];
    __shared__ float s_logit[CHc * HHc];
    __shared__ float s_alpha[CHc * HHc];
    __shared__ int   s_src[CHc];
    __shared__ int   s_tab[CHc];

    const int r0 = g_rowptr[n], r1 = g_rowptr[n + 1];
    const int deg = r1 - r0;
    const float inv = 1.0f / (float)(deg > 1 ? deg : 1);

    float c0 = (float)g_hist[n * NTc + 0];
    float c1 = (float)g_hist[n * NTc + 1];
    float c2 = (float)g_hist[n * NTc + 2];
    float c3 = (float)g_hist[n * NTc + 3];
    float c4 = (float)g_hist[n * NTc + 4];

    const float* tb = g_table + loff;
    {
        int j8 = tid * 8;
        uint4 raw = *reinterpret_cast<const uint4*>(g_xlr + (size_t)n * N2c + HDc + j8);
        __half2 p0 = *reinterpret_cast<__half2*>(&raw.x);
        __half2 p1 = *reinterpret_cast<__half2*>(&raw.y);
        __half2 p2 = *reinterpret_cast<__half2*>(&raw.z);
        __half2 p3 = *reinterpret_cast<__half2*>(&raw.w);
        s_xr[j8 + 0] = __half2float(p0.x); s_xr[j8 + 1] = __half2float(p0.y);
        s_xr[j8 + 2] = __half2float(p1.x); s_xr[j8 + 3] = __half2float(p1.y);
        s_xr[j8 + 4] = __half2float(p2.x); s_xr[j8 + 5] = __half2float(p2.y);
        s_xr[j8 + 6] = __half2float(p3.x); s_xr[j8 + 7] = __half2float(p3.y);
    }
    #pragma unroll
    for (int u = 0; u < 8; ++u) {
        int j = tid + u * 256;
        s_att[j] = att_l[j];
        float v = c0 * tb[0 * HDc + j];
        v = fmaf(c1, tb[1 * HDc + j], v);
        v = fmaf(c2, tb[2 * HDc + j], v);
        v = fmaf(c3, tb[3 * HDc + j], v);
        v = fmaf(c4, tb[4 * HDc + j], v);
        s_lee[j] = v * inv;
    }
    __syncthreads();

    float m_h = -1e30f, d_h = 0.f;     // per-head running state (replicated in warp w)
    float acc[8];
    #pragma unroll
    for (int i = 0; i < 8; ++i) acc[i] = 0.f;

    const int total = deg + 1;          // edges + self-loop (last)
    for (int cst = 0; cst < total; cst += CHc) {
        const int items = min(CHc, total - cst);

        // phase 0: load chunk edge metadata
        if (tid < items) {
            int idx = r0 + cst + tid;
            if (idx < r1) {
                int e = g_eid[idx];
                s_src[tid] = edge_index[e];
                s_tab[tid] = edge_attr[e];
            } else {
                s_src[tid] = n;
                s_tab[tid] = -1;
            }
        }
        __syncthreads();

        // phase 1: edge-parallel logit computation (warp j-strided over edges)
        for (int j = w; j < items; j += HHc) {
            const int src = s_src[j];
            const int t = s_tab[j];
            const float* tabp = (t < 0) ? s_lee : (tb + (size_t)t * HDc);
            float part[HHc];
            #pragma unroll
            for (int h = 0; h < HHc; ++h) {
                const int ch = h * DHc + lane * 8;
                uint4 raw = *reinterpret_cast<const uint4*>(g_xlr + (size_t)src * N2c + ch);
                __half2 p0 = *reinterpret_cast<__half2*>(&raw.x);
                __half2 p1 = *reinterpret_cast<__half2*>(&raw.y);
                __half2 p2 = *reinterpret_cast<__half2*>(&raw.z);
                __half2 p3 = *reinterpret_cast<__half2*>(&raw.w);
                float xv[8];
                xv[0] = __half2float(p0.x); xv[1] = __half2float(p0.y);
                xv[2] = __half2float(p1.x); xv[3] = __half2float(p1.y);
                xv[4] = __half2float(p2.x); xv[5] = __half2float(p2.y);
                xv[6] = __half2float(p3.x); xv[7] = __half2float(p3.y);
                float s = 0.f;
                #pragma unroll
                for (int i = 0; i < 8; ++i) {
                    float z = xv[i] + s_xr[ch + i] + tabp[ch + i];
                    z = z > 0.f ? z : 0.2f * z;
                    s = fmaf(z, s_att[ch + i], s);
                }
                part[h] = s;
            }
            #pragma unroll
            for (int o = 16; o > 0; o >>= 1)
                #pragma unroll
                for (int h = 0; h < HHc; ++h)
                    part[h] += __shfl_xor_sync(0xffffffffu, part[h], o);
            if (lane == 0) {
                #pragma unroll
                for (int h = 0; h < HHc; ++h) s_logit[j * HHc + h] = part[h];
            }
        }
        __syncthreads();

        // phase 2: warp-per-head chunk softmax, online-combined at chunk level
        {
            float l1 = (lane < items) ? s_logit[lane * HHc + w] : -1e30f;
            float l2 = (lane + 32 < items) ? s_logit[(lane + 32) * HHc + w] : -1e30f;
            float cm = fmaxf(l1, l2);
            #pragma unroll
            for (int o = 16; o > 0; o >>= 1)
                cm = fmaxf(cm, __shfl_xor_sync(0xffffffffu, cm, o));
            float mn = fmaxf(m_h, cm);
            float sc = __expf(m_h - mn);
            float p1 = (lane < items) ? __expf(l1 - mn) : 0.f;
            float p2 = (lane + 32 < items) ? __expf(l2 - mn) : 0.f;
            if (lane < items) s_alpha[lane * HHc + w] = p1;
            if (lane + 32 < items) s_alpha[(lane + 32) * HHc + w] = p2;
            float cs = p1 + p2;
            #pragma unroll
            for (int o = 16; o > 0; o >>= 1)
                cs += __shfl_xor_sync(0xffffffffu, cs, o);
            d_h = d_h * sc + cs;
            m_h = mn;
            #pragma unroll
            for (int i = 0; i < 8; ++i) acc[i] *= sc;
        }
        __syncthreads();

        // phase 3: channel-parallel weighted accumulation (xl rows L1-hot)
        for (int j = 0; j < items; ++j) {
            const float a = s_alpha[j * HHc + w];
            const int src = s_src[j];
            uint4 raw = *reinterpret_cast<const uint4*>(g_xlr + (size_t)src * N2c + base);
            __half2 p0 = *reinterpret_cast<__half2*>(&raw.x);
            __half2 p1 = *reinterpret_cast<__half2*>(&raw.y);
            __half2 p2 = *reinterpret_cast<__half2*>(&raw.z);
            __half2 p3 = *reinterpret_cast<__half2*>(&raw.w);
            acc[0] = fmaf(a, __half2float(p0.x), acc[0]);
            acc[1] = fmaf(a, __half2float(p0.y), acc[1]);
            acc[2] = fmaf(a, __half2float(p1.x), acc[2]);
            acc[3] = fmaf(a, __half2float(p1.y), acc[3]);
            acc[4] = fmaf(a, __half2float(p2.x), acc[4]);
            acc[5] = fmaf(a, __half2float(p2.y), acc[5]);
            acc[6] = fmaf(a, __half2float(p3.x), acc[6]);
            acc[7] = fmaf(a, __half2float(p3.y), acc[7]);
        }
        __syncthreads();   // protect s_src/s_logit before next chunk
    }

    const float invd = 1.0f / d_h;
    #pragma unroll
    for (int i = 0; i < 8; ++i) s_out[base + i] = acc[i] * invd;
    __syncthreads();

    {
        int c = tid;
        float v = 0.f;
        #pragma unroll
        for (int h = 0; h < HHc; ++h) v += s_out[h * DHc + c];
        v = fmaf(v, 0.125f, bgat_l[c]);
        v = fmaxf(v, 0.f);
        __nv_bfloat16 hi = __float2bfloat16(v);
        __nv_bfloat16 lo = __float2bfloat16(v - __bfloat162float(hi));
        __nv_bfloat16* p = packH + (size_t)n * (3 * DHc) + c;
        p[0]        = hi;
        p[DHc]      = lo;
        p[2 * DHc]  = hi;
    }
}

// ---------------- host orchestration ----------------
extern "C" void kernel_launch(void* const* d_in, const int* in_sizes, int n_in,
                              void* d_out, int out_size) {
    const float* x         = (const float*)d_in[0];
    const int*   edge_index= (const int*)  d_in[1];
    const int*   edge_attr = (const int*)  d_in[2];
    const int*   node_types= (const int*)  d_in[3];
    const float* W_in      = (const float*)d_in[4];
    const float* b_in      = (const float*)d_in[5];
    const float* node_emb  = (const float*)d_in[6];
    const float* edge_emb  = (const float*)d_in[7];
    const float* Wl        = (const float*)d_in[8];
    const float* bl        = (const float*)d_in[9];
    const float* Wr        = (const float*)d_in[10];
    const float* br        = (const float*)d_in[11];
    const float* We        = (const float*)d_in[12];
    const float* att       = (const float*)d_in[13];
    const float* b_gat     = (const float*)d_in[14];
    const float* W_out     = (const float*)d_in[15];
    const float* b_out     = (const float*)d_in[16];
    float* out = (float*)d_out;

    __half* xlr;    cudaGetSymbolAddress((void**)&xlr, g_xlr);
    __nv_bfloat16* Apk; cudaGetSymbolAddress((void**)&Apk, g_Apack);
    __nv_bfloat16* Hpk; cudaGetSymbolAddress((void**)&Hpk, g_hpack);
    __nv_bfloat16* Bpk; cudaGetSymbolAddress((void**)&Bpk, g_Bpack);

    cudaFuncSetAttribute(k_gemm_mma, cudaFuncAttributeMaxDynamicSharedMemorySize, GEMM_SMEM);
    cudaFuncSetAttribute(k_gemm_big, cudaFuncAttributeMaxDynamicSharedMemorySize, BGEMM_SMEM);

    // 1: pack everything
    k_pack_all<<<Nn + 256 + 3072 + 64 + 120, 256>>>(x, W_in, Wl, Wr, W_out,
                                                    edge_emb, We, Apk, Bpk);
    // 2: CSR zero
    k_zero<<<(Nn * NTc + 255) / 256, 256>>>();
    // 3: input projection -> packed h0
    k_gemm_mma<<<dim3(2, 64), 256, GEMM_SMEM>>>(
        Apk, Bpk + OFF_WIN, b_in, nullptr, 3 * DINc, DHc, node_emb, node_types, Hpk);
    // 4: merged xl|xr GEMM layer 0   <- ncu capture slot
    k_gemm_big<<<dim3(N2c / 256, 64), 256, BGEMM_SMEM>>>(
        Hpk, Bpk + OFF_WLR(0), bl, br, HDc, xlr, 3 * DHc, N2c);
    // 5-8: finish CSR
    k_count<<<(Ee + 255) / 256, 256>>>(edge_index, edge_attr);
    k_scan<<<1, 256>>>();
    k_fill<<<(Ee + 255) / 256, 256>>>(edge_index);
    k_sort<<<(Nn + 255) / 256, 256>>>();

    for (int l = 0; l < LLc; ++l) {
        if (l > 0) {
            k_gemm_big<<<dim3(N2c / 256, 64), 256, BGEMM_SMEM>>>(
                Hpk, Bpk + OFF_WLR(l), bl + (size_t)l * HDc, br + (size_t)l * HDc,
                HDc, xlr, 3 * DHc, N2c);
        }
        k_edge<<<Nn, 256>>>(edge_index, edge_attr,
                            att + (size_t)l * HHc * DHc,
                            b_gat + (size_t)l * DHc, l * NTc * HDc, Hpk);
    }

    // output projection -> d_out fp32
    k_gemm_mma<<<dim3(2, 64), 256, GEMM_SMEM>>>(
        Hpk, Bpk + OFF_WOUT, b_out, out, 3 * DHc, DHc, nullptr, nullptr, nullptr);

    (void)in_sizes; (void)n_in; (void)out_size;
}

// round 8
// speedup vs baseline: 1.7369x; 1.7369x over previous
#include <cuda_runtime.h>
#include <cuda_fp16.h>
#include <math.h>
#include <stdint.h>

// Problem constants
#define Nn   8192
#define Ee   32768
#define DINc 1024
#define DHc  256
#define HHc  8
#define LLc  3
#define HDc  2048   // H*DH
#define NTc  5
#define N2c  4096   // merged Wl|Wr output width

// ---------------- device scratch ----------------
__device__ __half g_xlr[(size_t)Nn * N2c];         // merged xl|xr, fp16 (L2-resident)
__device__ float g_table[LLc * NTc * HDc];
__device__ int   g_deg[Nn];
__device__ int   g_hist[Nn * NTc];
__device__ int   g_rowptr[Nn + 1];
__device__ int   g_woff[Nn];
__device__ int   g_eid[Ee];

// fp16x2 packed operands: A rows [Ah|Al] (2K), W cols [Bh|Bh] (2K, transposed)
__device__ __half g_Apack[(size_t)Nn * 2 * DINc];
__device__ __half g_hpack[(size_t)Nn * 2 * DHc];
__device__ __half g_Bpack[7000000];

#define OFF_WIN  0
#define SZ_WIN   (DHc * 2 * DINc)                 // 524288
#define SZ_L     ((size_t)N2c * 2 * DHc)          // 2097152
#define OFF_WLR(l) (SZ_WIN + (size_t)(l) * SZ_L)
#define OFF_WOUT (SZ_WIN + (size_t)3 * SZ_L)

// ---------------- PTX helpers ----------------
__device__ __forceinline__ uint32_t smem_u32(const void* p) {
    uint32_t a;
    asm("{ .reg .u64 t; cvta.to.shared.u64 t, %1; cvt.u32.u64 %0, t; }" : "=r"(a) : "l"(p));
    return a;
}
__device__ __forceinline__ void cp16(uint32_t d, const void* g) {
    asm volatile("cp.async.cg.shared.global [%0], [%1], 16;" :: "r"(d), "l"(g));
}
__device__ __forceinline__ void ldsm_x4(uint32_t* r, uint32_t addr) {
    asm volatile("ldmatrix.sync.aligned.m8n8.x4.shared.b16 {%0,%1,%2,%3}, [%4];"
                 : "=r"(r[0]), "=r"(r[1]), "=r"(r[2]), "=r"(r[3]) : "r"(addr));
}
__device__ __forceinline__ void mma_f16(float* c, const uint32_t* a, uint32_t b0, uint32_t b1) {
    asm volatile(
        "mma.sync.aligned.m16n8k16.row.col.f32.f16.f16.f32 "
        "{%0,%1,%2,%3}, {%4,%5,%6,%7}, {%8,%9}, {%0,%1,%2,%3};"
        : "+f"(c[0]), "+f"(c[1]), "+f"(c[2]), "+f"(c[3])
        : "r"(a[0]), "r"(a[1]), "r"(a[2]), "r"(a[3]), "r"(b0), "r"(b1));
}

// ---------------- CSR build ----------------
__global__ void k_zero() {
    int i = blockIdx.x * 256 + threadIdx.x;
    if (i < Nn) g_deg[i] = 0;
    if (i < Nn * NTc) g_hist[i] = 0;
}
__global__ void k_count(const int* __restrict__ ei, const int* __restrict__ ea) {
    int e = blockIdx.x * 256 + threadIdx.x;
    if (e < Ee) {
        int dst = ei[Ee + e];
        atomicAdd(&g_deg[dst], 1);
        atomicAdd(&g_hist[dst * NTc + ea[e]], 1);
    }
}
__global__ void k_scan() {
    __shared__ int part[256];
    int tid = threadIdx.x;
    int base = tid * 32;
    int s = 0;
    for (int i = 0; i < 32; ++i) s += g_deg[base + i];
    part[tid] = s;
    __syncthreads();
    for (int off = 1; off < 256; off <<= 1) {
        int v = (tid >= off) ? part[tid - off] : 0;
        __syncthreads();
        part[tid] += v;
        __syncthreads();
    }
    int run = (tid == 0) ? 0 : part[tid - 1];
    for (int i = 0; i < 32; ++i) {
        int n = base + i;
        g_rowptr[n] = run;
        g_woff[n] = run;
        run += g_deg[n];
    }
    if (tid == 255) g_rowptr[Nn] = run;
}
__global__ void k_fill(const int* __restrict__ ei) {
    int e = blockIdx.x * 256 + threadIdx.x;
    if (e < Ee) {
        int dst = ei[Ee + e];
        int pos = atomicAdd(&g_woff[dst], 1);
        g_eid[pos] = e;
    }
}
__global__ void k_sort() {
    int n = blockIdx.x * 256 + threadIdx.x;
    if (n < Nn) {
        int r0 = g_rowptr[n], r1 = g_rowptr[n + 1];
        for (int i = r0 + 1; i < r1; ++i) {
            int v = g_eid[i];
            int j = i - 1;
            while (j >= r0 && g_eid[j] > v) { g_eid[j + 1] = g_eid[j]; --j; }
            g_eid[j + 1] = v;
        }
    }
}

// ---------------- fused packing: x, all weights, all tables ----------------
// block ranges: [0,8192) x-rows | [8192,8448) W_in | [8448,11520) Wl/Wr | [11520,11584) W_out
//               [11584,11704) table segments
__global__ void __launch_bounds__(256)
k_pack_all(const float* __restrict__ x,
           const float* __restrict__ W_in,
           const float* __restrict__ Wl, const float* __restrict__ Wr,
           const float* __restrict__ W_out,
           const float* __restrict__ edge_emb, const float* __restrict__ We,
           __half* __restrict__ Apk, __half* __restrict__ Bpk) {
    const int bid = blockIdx.x;
    const int tid = threadIdx.x;

    if (bid < Nn) {
        // pack x row -> [Ah|Al]
        const float4 v = *reinterpret_cast<const float4*>(x + (size_t)bid * DINc + tid * 4);
        __half h0 = __float2half_rn(v.x), h1 = __float2half_rn(v.y);
        __half h2 = __float2half_rn(v.z), h3 = __float2half_rn(v.w);
        __half2 hp0 = {h0, h1}, hp1 = {h2, h3};
        __half2 lp0 = {__float2half_rn(v.x - __half2float(h0)),
                       __float2half_rn(v.y - __half2float(h1))};
        __half2 lp1 = {__float2half_rn(v.z - __half2float(h2)),
                       __float2half_rn(v.w - __half2float(h3))};
        __half* p = Apk + (size_t)bid * 2 * DINc + tid * 4;
        reinterpret_cast<__half2*>(p)[0] = hp0;
        reinterpret_cast<__half2*>(p)[1] = hp1;
        reinterpret_cast<__half2*>(p + DINc)[0] = lp0;
        reinterpret_cast<__half2*>(p + DINc)[1] = lp1;
        return;
    }
    if (bid < Nn + 256 + 3072 + 64) {
        // weight tile pack: 32x32 transpose, [Bh|Bh]
        const float* W; __half* P; int K, N, nb, kb;
        int id = bid - Nn;
        if (id < 256) {
            W = W_in; P = Bpk + OFF_WIN; K = DINc; N = DHc;
            nb = id & 7; kb = id >> 3;
        } else if (id < 256 + 3072) {
            int id2 = id - 256;
            int mat = id2 >> 9;
            int t = id2 & 511;
            int l = mat >> 1, side = mat & 1;
            W = (side == 0 ? Wl : Wr) + (size_t)l * DHc * HDc;
            P = Bpk + OFF_WLR(l) + (size_t)side * HDc * 2 * DHc;
            K = DHc; N = HDc;
            nb = t & 63; kb = t >> 6;
        } else {
            int id2 = id - 256 - 3072;
            W = W_out; P = Bpk + OFF_WOUT; K = DHc; N = DHc;
            nb = id2 & 7; kb = id2 >> 3;
        }
        __shared__ float tbuf[32][33];
        int tx = tid & 31, ty = tid >> 5;
        #pragma unroll
        for (int i = 0; i < 32; i += 8)
            tbuf[ty + i][tx] = W[(size_t)(kb * 32 + ty + i) * N + nb * 32 + tx];
        __syncthreads();
        int K2 = 2 * K;
        #pragma unroll
        for (int i = 0; i < 32; i += 8) {
            int n = nb * 32 + ty + i;
            int k = kb * 32 + tx;
            __half hi = __float2half_rn(tbuf[tx][ty + i]);
            P[(size_t)n * K2 + k]     = hi;
            P[(size_t)n * K2 + K + k] = hi;
        }
        return;
    }
    {
        // tables: table[l][t][j] = edge_emb[t] . We[l][:,j]  (fp32, exact)
        int id = bid - (Nn + 256 + 3072 + 64);
        int lt = id >> 3;
        int jb = id & 7;
        int l = lt / NTc, t = lt % NTc;
        int j = jb * 256 + tid;
        const float* w = We + (size_t)l * DHc * HDc + j;
        const float* e = edge_emb + t * DHc;
        float s = 0.f;
        #pragma unroll 4
        for (int k = 0; k < DHc; ++k) s = fmaf(e[k], w[(size_t)k * HDc], s);
        g_table[(size_t)l * NTc * HDc + t * HDc + j] = s;
    }
}

// ---------------- GEMM kernel 1 (proj): CTA 128x128, warp 32x64, 3-stage, 2 CTA/SM ----
#define GSTAGE 3
#define STG_BYTES 32768
#define GEMM_SMEM (GSTAGE * STG_BYTES)

__global__ void __launch_bounds__(256, 2)
k_gemm_mma(const __half* __restrict__ A, const __half* __restrict__ B,
           const float* __restrict__ bias, float* __restrict__ C, int Ktot, int Nc,
           const float* __restrict__ emb, const int* __restrict__ types,
           __half* __restrict__ packA) {
    extern __shared__ __align__(1024) char smem[];
    const uint32_t sb = smem_u32(smem);
    const int tid = threadIdx.x;
    const int lane = tid & 31, w = tid >> 5;
    const int wm = w & 3, wn = w >> 2;
    const int row0 = blockIdx.y * 128;
    const int col0 = blockIdx.x * 128;
    const int nch = Ktot >> 6;

    float acc[2][8][4];
    #pragma unroll
    for (int i = 0; i < 2; ++i)
        #pragma unroll
        for (int j = 0; j < 8; ++j)
            #pragma unroll
            for (int q = 0; q < 4; ++q) acc[i][j][q] = 0.f;

    uint32_t sm_off[4];
    const __half* gA[4];
    const __half* gB[4];
    #pragma unroll
    for (int u = 0; u < 4; ++u) {
        int i = tid + u * 256;
        int r = i >> 3, seg = i & 7;
        uint32_t off = (uint32_t)(r * 128 + seg * 16);
        sm_off[u] = off ^ ((off >> 3) & 0x70);
        gA[u] = A + (size_t)(row0 + r) * Ktot + (seg << 3);
        gB[u] = B + (size_t)(col0 + r) * Ktot + (seg << 3);
    }
    auto load_chunk = [&](int c) {
        const uint32_t s = sb + (uint32_t)((c % GSTAGE) * STG_BYTES);
        const int kof = c << 6;
        #pragma unroll
        for (int u = 0; u < 4; ++u) cp16(s + sm_off[u], gA[u] + kof);
        #pragma unroll
        for (int u = 0; u < 4; ++u) cp16(s + 16384 + sm_off[u], gB[u] + kof);
        asm volatile("cp.async.commit_group;");
    };
    #pragma unroll
    for (int c = 0; c < GSTAGE - 1; ++c) load_chunk(c);

    uint32_t a_base[2], a_swz[2];
    #pragma unroll
    for (int mb = 0; mb < 2; ++mb) {
        int row = wm * 32 + mb * 16 + (lane & 15);
        a_base[mb] = (uint32_t)(row * 128 + ((lane >> 4) << 4));
        a_swz[mb] = (uint32_t)((row & 7) << 4);
    }
    uint32_t b_base[4], b_swz[4];
    #pragma unroll
    for (int nb = 0; nb < 4; ++nb) {
        int row = wn * 64 + nb * 16 + (lane & 7) + ((lane >> 4) << 3);
        b_base[nb] = (uint32_t)(row * 128 + (((lane >> 3) & 1) << 4));
        b_swz[nb] = (uint32_t)((row & 7) << 4);
    }

    for (int c = 0; c < nch; ++c) {
        asm volatile("cp.async.wait_group %0;" :: "n"(GSTAGE - 2));
        __syncthreads();
        if (c + GSTAGE - 1 < nch) load_chunk(c + GSTAGE - 1);
        else asm volatile("cp.async.commit_group;");
        const uint32_t stb = sb + (uint32_t)((c % GSTAGE) * STG_BYTES);
        #pragma unroll
        for (int kk = 0; kk < 4; ++kk) {
            const uint32_t kby = (uint32_t)(kk * 32);
            uint32_t a[2][4];
            #pragma unroll
            for (int mb = 0; mb < 2; ++mb)
                ldsm_x4(a[mb], stb + ((a_base[mb] + kby) ^ a_swz[mb]));
            uint32_t b[4][4];
            #pragma unroll
            for (int nb = 0; nb < 4; ++nb)
                ldsm_x4(b[nb], stb + 16384 + ((b_base[nb] + kby) ^ b_swz[nb]));
            #pragma unroll
            for (int mb = 0; mb < 2; ++mb)
                #pragma unroll
                for (int nb = 0; nb < 4; ++nb) {
                    mma_f16(acc[mb][2 * nb],     a[mb], b[nb][0], b[nb][1]);
                    mma_f16(acc[mb][2 * nb + 1], a[mb], b[nb][2], b[nb][3]);
                }
        }
    }

    const int r_base = row0 + wm * 32 + (lane >> 2);
    const int c_base = col0 + wn * 64 + ((lane & 3) << 1);
    const int K2 = 2 * Nc;
    #pragma unroll
    for (int mb = 0; mb < 2; ++mb) {
        const int r1 = r_base + mb * 16;
        const int r2 = r1 + 8;
        #pragma unroll
        for (int nt = 0; nt < 8; ++nt) {
            const int col = c_base + nt * 8;
            float bx = bias[col], by = bias[col + 1];
            float e1x = 0.f, e1y = 0.f, e2x = 0.f, e2y = 0.f;
            if (emb) {
                const float* em1 = emb + (size_t)types[r1] * Nc + col;
                const float* em2 = emb + (size_t)types[r2] * Nc + col;
                e1x = em1[0]; e1y = em1[1]; e2x = em2[0]; e2y = em2[1];
            }
            float v00 = acc[mb][nt][0] + bx + e1x;
            float v01 = acc[mb][nt][1] + by + e1y;
            float v10 = acc[mb][nt][2] + bx + e2x;
            float v11 = acc[mb][nt][3] + by + e2y;
            if (C) {
                float2 t0 = {v00, v01}, t1 = {v10, v11};
                *reinterpret_cast<float2*>(&C[(size_t)r1 * Nc + col]) = t0;
                *reinterpret_cast<float2*>(&C[(size_t)r2 * Nc + col]) = t1;
            }
            if (packA) {
                __half h00 = __float2half_rn(v00);
                __half h01 = __float2half_rn(v01);
                __half h10 = __float2half_rn(v10);
                __half h11 = __float2half_rn(v11);
                __half2 hp1 = {h00, h01};
                __half2 hp2 = {h10, h11};
                __half2 lp1 = {__float2half_rn(v00 - __half2float(h00)),
                               __float2half_rn(v01 - __half2float(h01))};
                __half2 lp2 = {__float2half_rn(v10 - __half2float(h10)),
                               __float2half_rn(v11 - __half2float(h11))};
                __half* p1 = packA + (size_t)r1 * K2 + col;
                __half* p2 = packA + (size_t)r2 * K2 + col;
                *reinterpret_cast<__half2*>(p1)      = hp1;
                *reinterpret_cast<__half2*>(p1 + Nc) = lp1;
                *reinterpret_cast<__half2*>(p2)      = hp2;
                *reinterpret_cast<__half2*>(p2 + Nc) = lp2;
            }
        }
    }
}

// ---------------- GEMM kernel 2 (merged xl|xr): CTA 128x256, warp 64x64, 4-stage ----
#define BGSTAGE 4
#define BSTG_BYTES 49152
#define BGEMM_SMEM (BGSTAGE * BSTG_BYTES)

__global__ void __launch_bounds__(256, 1)
k_gemm_big(const __half* __restrict__ A, const __half* __restrict__ B,
           const float* __restrict__ bias, const float* __restrict__ bias2, int halfN,
           __half* __restrict__ C, int Ktot, int Nc) {
    extern __shared__ __align__(1024) char smem[];
    const uint32_t sb = smem_u32(smem);
    const int tid = threadIdx.x;
    const int lane = tid & 31, w = tid >> 5;
    const int wm = w & 1, wn = w >> 1;
    const int row0 = blockIdx.y * 128;
    const int col0 = blockIdx.x * 256;
    const int nch = Ktot >> 6;

    float acc[4][8][4];
    #pragma unroll
    for (int i = 0; i < 4; ++i)
        #pragma unroll
        for (int j = 0; j < 8; ++j)
            #pragma unroll
            for (int q = 0; q < 4; ++q) acc[i][j][q] = 0.f;

    uint32_t sm_offA[4], sm_offB[8];
    const __half* gA[4];
    const __half* gB[8];
    #pragma unroll
    for (int u = 0; u < 4; ++u) {
        int i = tid + u * 256;
        int r = i >> 3, seg = i & 7;
        uint32_t off = (uint32_t)(r * 128 + seg * 16);
        sm_offA[u] = off ^ ((off >> 3) & 0x70);
        gA[u] = A + (size_t)(row0 + r) * Ktot + (seg << 3);
    }
    #pragma unroll
    for (int u = 0; u < 8; ++u) {
        int i = tid + u * 256;
        int r = i >> 3, seg = i & 7;
        uint32_t off = (uint32_t)(r * 128 + seg * 16);
        sm_offB[u] = off ^ ((off >> 3) & 0x70);
        gB[u] = B + (size_t)(col0 + r) * Ktot + (seg << 3);
    }
    auto load_chunk = [&](int c) {
        const uint32_t s = sb + (uint32_t)((c % BGSTAGE) * BSTG_BYTES);
        const int kof = c << 6;
        #pragma unroll
        for (int u = 0; u < 4; ++u) cp16(s + sm_offA[u], gA[u] + kof);
        #pragma unroll
        for (int u = 0; u < 8; ++u) cp16(s + 16384 + sm_offB[u], gB[u] + kof);
        asm volatile("cp.async.commit_group;");
    };
    #pragma unroll
    for (int c = 0; c < BGSTAGE - 1; ++c) load_chunk(c);

    uint32_t a_base[4], a_swz[4];
    #pragma unroll
    for (int mb = 0; mb < 4; ++mb) {
        int row = wm * 64 + mb * 16 + (lane & 15);
        a_base[mb] = (uint32_t)(row * 128 + ((lane >> 4) << 4));
        a_swz[mb] = (uint32_t)((row & 7) << 4);
    }
    uint32_t b_base[4], b_swz[4];
    #pragma unroll
    for (int nb = 0; nb < 4; ++nb) {
        int row = wn * 64 + nb * 16 + (lane & 7) + ((lane >> 4) << 3);
        b_base[nb] = (uint32_t)(row * 128 + (((lane >> 3) & 1) << 4));
        b_swz[nb] = (uint32_t)((row & 7) << 4);
    }

    for (int c = 0; c < nch; ++c) {
        asm volatile("cp.async.wait_group %0;" :: "n"(BGSTAGE - 2));
        __syncthreads();
        if (c + BGSTAGE - 1 < nch) load_chunk(c + BGSTAGE - 1);
        else asm volatile("cp.async.commit_group;");
        const uint32_t stb = sb + (uint32_t)((c % BGSTAGE) * BSTG_BYTES);
        #pragma unroll
        for (int kk = 0; kk < 4; ++kk) {
            const uint32_t kby = (uint32_t)(kk * 32);
            uint32_t a[4][4];
            #pragma unroll
            for (int mb = 0; mb < 4; ++mb)
                ldsm_x4(a[mb], stb + ((a_base[mb] + kby) ^ a_swz[mb]));
            uint32_t b[4][4];
            #pragma unroll
            for (int nb = 0; nb < 4; ++nb)
                ldsm_x4(b[nb], stb + 16384 + ((b_base[nb] + kby) ^ b_swz[nb]));
            #pragma unroll
            for (int mb = 0; mb < 4; ++mb)
                #pragma unroll
                for (int nb = 0; nb < 4; ++nb) {
                    mma_f16(acc[mb][2 * nb],     a[mb], b[nb][0], b[nb][1]);
                    mma_f16(acc[mb][2 * nb + 1], a[mb], b[nb][2], b[nb][3]);
                }
        }
    }

    const float* bp = bias;
    int cadj = 0;
    if (bias2 && col0 >= halfN) { bp = bias2; cadj = halfN; }
    const int r_base = row0 + wm * 64 + (lane >> 2);
    const int c_base = col0 + wn * 64 + ((lane & 3) << 1);
    #pragma unroll
    for (int mb = 0; mb < 4; ++mb) {
        const int r1 = r_base + mb * 16;
        const int r2 = r1 + 8;
        #pragma unroll
        for (int nt = 0; nt < 8; ++nt) {
            const int col = c_base + nt * 8;
            float bx = bp[col - cadj], by = bp[col + 1 - cadj];
            __half2 t0 = __floats2half2_rn(acc[mb][nt][0] + bx, acc[mb][nt][1] + by);
            __half2 t1 = __floats2half2_rn(acc[mb][nt][2] + bx, acc[mb][nt][3] + by);
            *reinterpret_cast<__half2*>(&C[(size_t)r1 * Nc + col]) = t0;
            *reinterpret_cast<__half2*>(&C[(size_t)r2 * Nc + col]) = t1;
        }
    }
}

// ---------------- fused GATv2 edge kernel (R6 form: per-edge online, prefetched) ----
__global__ void __launch_bounds__(256)
k_edge(const int* __restrict__ edge_index, const int* __restrict__ edge_attr,
       const float* __restrict__ att_l, const float* __restrict__ bgat_l,
       int loff, __half* __restrict__ packH) {
    const int n = blockIdx.x;
    const int tid = threadIdx.x;
    const int lane = tid & 31;
    const int base = ((tid >> 5) << 8) + (lane << 3);

    __shared__ float s_xr[HDc];
    __shared__ float s_att[HDc];
    __shared__ float s_lee[HDc];
    __shared__ float s_out[HDc];

    const int r0 = g_rowptr[n], r1 = g_rowptr[n + 1];
    const int deg = r1 - r0;
    const float inv = 1.0f / (float)(deg > 1 ? deg : 1);

    float c0 = (float)g_hist[n * NTc + 0];
    float c1 = (float)g_hist[n * NTc + 1];
    float c2 = (float)g_hist[n * NTc + 2];
    float c3 = (float)g_hist[n * NTc + 3];
    float c4 = (float)g_hist[n * NTc + 4];

    const float* tb = g_table + loff;
    {
        int j8 = tid * 8;
        uint4 raw = *reinterpret_cast<const uint4*>(g_xlr + (size_t)n * N2c + HDc + j8);
        __half2 p0 = *reinterpret_cast<__half2*>(&raw.x);
        __half2 p1 = *reinterpret_cast<__half2*>(&raw.y);
        __half2 p2 = *reinterpret_cast<__half2*>(&raw.z);
        __half2 p3 = *reinterpret_cast<__half2*>(&raw.w);
        s_xr[j8 + 0] = __half2float(p0.x); s_xr[j8 + 1] = __half2float(p0.y);
        s_xr[j8 + 2] = __half2float(p1.x); s_xr[j8 + 3] = __half2float(p1.y);
        s_xr[j8 + 4] = __half2float(p2.x); s_xr[j8 + 5] = __half2float(p2.y);
        s_xr[j8 + 6] = __half2float(p3.x); s_xr[j8 + 7] = __half2float(p3.y);
    }
    #pragma unroll
    for (int u = 0; u < 8; ++u) {
        int j = tid + u * 256;
        s_att[j] = att_l[j];
        float v = c0 * tb[0 * HDc + j];
        v = fmaf(c1, tb[1 * HDc + j], v);
        v = fmaf(c2, tb[2 * HDc + j], v);
        v = fmaf(c3, tb[3 * HDc + j], v);
        v = fmaf(c4, tb[4 * HDc + j], v);
        s_lee[j] = v * inv;
    }
    __syncthreads();

    float m = -1e30f, d = 0.f;
    float acc[8];
    #pragma unroll
    for (int i = 0; i < 8; ++i) acc[i] = 0.f;

    int s_cur = n, t_cur = -1;
    if (r0 < r1) {
        int e = g_eid[r0];
        s_cur = edge_index[e];
        t_cur = edge_attr[e];
    }
    for (int idx = r0; idx <= r1; ++idx) {
        const bool isloop = (idx == r1);
        uint4 raw = *reinterpret_cast<const uint4*>(g_xlr + (size_t)s_cur * N2c + base);
        int s_nxt = n, t_nxt = -1;
        if (idx + 1 < r1) {
            int e = g_eid[idx + 1];
            s_nxt = edge_index[e];
            t_nxt = edge_attr[e];
        }
        __half2 p0 = *reinterpret_cast<__half2*>(&raw.x);
        __half2 p1 = *reinterpret_cast<__half2*>(&raw.y);
        __half2 p2 = *reinterpret_cast<__half2*>(&raw.z);
        __half2 p3 = *reinterpret_cast<__half2*>(&raw.w);
        float xlv[8];
        xlv[0] = __half2float(p0.x); xlv[1] = __half2float(p0.y);
        xlv[2] = __half2float(p1.x); xlv[3] = __half2float(p1.y);
        xlv[4] = __half2float(p2.x); xlv[5] = __half2float(p2.y);
        xlv[6] = __half2float(p3.x); xlv[7] = __half2float(p3.y);

        const float* tab = isloop ? (s_lee + base) : (tb + (size_t)t_cur * HDc + base);
        float part = 0.f;
        #pragma unroll
        for (int i = 0; i < 8; ++i) {
            float z = xlv[i] + s_xr[base + i] + tab[i];
            z = z > 0.f ? z : 0.2f * z;
            part = fmaf(z, s_att[base + i], part);
        }
        #pragma unroll
        for (int o = 16; o > 0; o >>= 1)
            part += __shfl_xor_sync(0xffffffffu, part, o);

        float mn = fmaxf(m, part);
        float sc = __expf(m - mn);
        float p  = __expf(part - mn);
        d = d * sc + p;
        #pragma unroll
        for (int i = 0; i < 8; ++i) acc[i] = fmaf(acc[i], sc, p * xlv[i]);
        m = mn;
        s_cur = s_nxt; t_cur = t_nxt;
    }

    float invd = 1.0f / d;
    #pragma unroll
    for (int i = 0; i < 8; ++i) s_out[base + i] = acc[i] * invd;
    __syncthreads();

    {
        int c = tid;
        float v = 0.f;
        #pragma unroll
        for (int h = 0; h < HHc; ++h) v += s_out[h * DHc + c];
        v = fmaf(v, 0.125f, bgat_l[c]);
        v = fmaxf(v, 0.f);
        __half hi = __float2half_rn(v);
        __half lo = __float2half_rn(v - __half2float(hi));
        __half* p = packH + (size_t)n * (2 * DHc) + c;
        p[0]   = hi;
        p[DHc] = lo;
    }
}

// ---------------- host orchestration ----------------
extern "C" void kernel_launch(void* const* d_in, const int* in_sizes, int n_in,
                              void* d_out, int out_size) {
    const float* x         = (const float*)d_in[0];
    const int*   edge_index= (const int*)  d_in[1];
    const int*   edge_attr = (const int*)  d_in[2];
    const int*   node_types= (const int*)  d_in[3];
    const float* W_in      = (const float*)d_in[4];
    const float* b_in      = (const float*)d_in[5];
    const float* node_emb  = (const float*)d_in[6];
    const float* edge_emb  = (const float*)d_in[7];
    const float* Wl        = (const float*)d_in[8];
    const float* bl        = (const float*)d_in[9];
    const float* Wr        = (const float*)d_in[10];
    const float* br        = (const float*)d_in[11];
    const float* We        = (const float*)d_in[12];
    const float* att       = (const float*)d_in[13];
    const float* b_gat     = (const float*)d_in[14];
    const float* W_out     = (const float*)d_in[15];
    const float* b_out     = (const float*)d_in[16];
    float* out = (float*)d_out;

    __half* xlr;    cudaGetSymbolAddress((void**)&xlr, g_xlr);
    __half* Apk;    cudaGetSymbolAddress((void**)&Apk, g_Apack);
    __half* Hpk;    cudaGetSymbolAddress((void**)&Hpk, g_hpack);
    __half* Bpk;    cudaGetSymbolAddress((void**)&Bpk, g_Bpack);

    cudaFuncSetAttribute(k_gemm_mma, cudaFuncAttributeMaxDynamicSharedMemorySize, GEMM_SMEM);
    cudaFuncSetAttribute(k_gemm_big, cudaFuncAttributeMaxDynamicSharedMemorySize, BGEMM_SMEM);

    // 1: pack everything
    k_pack_all<<<Nn + 256 + 3072 + 64 + 120, 256>>>(x, W_in, Wl, Wr, W_out,
                                                    edge_emb, We, Apk, Bpk);
    // 2: CSR zero
    k_zero<<<(Nn * NTc + 255) / 256, 256>>>();
    // 3: input projection -> packed h0  (Ktot = 2*DINc = 2048)
    k_gemm_mma<<<dim3(2, 64), 256, GEMM_SMEM>>>(
        Apk, Bpk + OFF_WIN, b_in, nullptr, 2 * DINc, DHc, node_emb, node_types, Hpk);
    // 4: merged xl|xr GEMM layer 0 (Ktot = 512)  <- ncu capture slot
    k_gemm_big<<<dim3(N2c / 256, 64), 256, BGEMM_SMEM>>>(
        Hpk, Bpk + OFF_WLR(0), bl, br, HDc, xlr, 2 * DHc, N2c);
    // 5-8: finish CSR
    k_count<<<(Ee + 255) / 256, 256>>>(edge_index, edge_attr);
    k_scan<<<1, 256>>>();
    k_fill<<<(Ee + 255) / 256, 256>>>(edge_index);
    k_sort<<<(Nn + 255) / 256, 256>>>();

    for (int l = 0; l < LLc; ++l) {
        if (l > 0) {
            k_gemm_big<<<dim3(N2c / 256, 64), 256, BGEMM_SMEM>>>(
                Hpk, Bpk + OFF_WLR(l), bl + (size_t)l * HDc, br + (size_t)l * HDc,
                HDc, xlr, 2 * DHc, N2c);
        }
        k_edge<<<Nn, 256>>>(edge_index, edge_attr,
                            att + (size_t)l * HHc * DHc,
                            b_gat + (size_t)l * DHc, l * NTc * HDc, Hpk);
    }

    // output projection -> d_out fp32
    k_gemm_mma<<<dim3(2, 64), 256, GEMM_SMEM>>>(
        Hpk, Bpk + OFF_WOUT, b_out, out, 2 * DHc, DHc, nullptr, nullptr, nullptr);

    (void)in_sizes; (void)n_in; (void)out_size;
}

// round 9
// speedup vs baseline: 1.8815x; 1.0833x over previous
#include <cuda_runtime.h>
#include <cuda_fp16.h>
#include <math.h>
#include <stdint.h>

// Problem constants
#define Nn   8192
#define Ee   32768
#define DINc 1024
#define DHc  256
#define HHc  8
#define LLc  3
#define HDc  2048   // H*DH
#define NTc  5
#define N2c  4096   // merged Wl|Wr output width
#define EGc  8      // nodes per edge-kernel block

// ---------------- device scratch ----------------
__device__ __half g_xlr[(size_t)Nn * N2c];         // merged xl|xr, fp16 (L2-resident)
__device__ float g_table[LLc * NTc * HDc];
__device__ int   g_deg[Nn];
__device__ int   g_hist[Nn * NTc];
__device__ int   g_rowptr[Nn + 1];
__device__ int   g_woff[Nn];
__device__ int   g_eid[Ee];

// fp16x2 packed operands: A rows [Ah|Al] (2K), W cols [Bh|Bh] (2K, transposed)
__device__ __half g_Apack[(size_t)Nn * 2 * DINc];
__device__ __half g_hpack[(size_t)Nn * 2 * DHc];
__device__ __half g_Bpack[7000000];

#define OFF_WIN  0
#define SZ_WIN   (DHc * 2 * DINc)
#define SZ_L     ((size_t)N2c * 2 * DHc)
#define OFF_WLR(l) (SZ_WIN + (size_t)(l) * SZ_L)
#define OFF_WOUT (SZ_WIN + (size_t)3 * SZ_L)

// ---------------- PTX helpers ----------------
__device__ __forceinline__ uint32_t smem_u32(const void* p) {
    uint32_t a;
    asm("{ .reg .u64 t; cvta.to.shared.u64 t, %1; cvt.u32.u64 %0, t; }" : "=r"(a) : "l"(p));
    return a;
}
__device__ __forceinline__ void cp16(uint32_t d, const void* g) {
    asm volatile("cp.async.cg.shared.global [%0], [%1], 16;" :: "r"(d), "l"(g));
}
__device__ __forceinline__ void ldsm_x4(uint32_t* r, uint32_t addr) {
    asm volatile("ldmatrix.sync.aligned.m8n8.x4.shared.b16 {%0,%1,%2,%3}, [%4];"
                 : "=r"(r[0]), "=r"(r[1]), "=r"(r[2]), "=r"(r[3]) : "r"(addr));
}
__device__ __forceinline__ void mma_f16(float* c, const uint32_t* a, uint32_t b0, uint32_t b1) {
    asm volatile(
        "mma.sync.aligned.m16n8k16.row.col.f32.f16.f16.f32 "
        "{%0,%1,%2,%3}, {%4,%5,%6,%7}, {%8,%9}, {%0,%1,%2,%3};"
        : "+f"(c[0]), "+f"(c[1]), "+f"(c[2]), "+f"(c[3])
        : "r"(a[0]), "r"(a[1]), "r"(a[2]), "r"(a[3]), "r"(b0), "r"(b1));
}

// ---------------- CSR build ----------------
__global__ void k_zero() {
    int i = blockIdx.x * 256 + threadIdx.x;
    if (i < Nn) g_deg[i] = 0;
    if (i < Nn * NTc) g_hist[i] = 0;
}
__global__ void k_count(const int* __restrict__ ei, const int* __restrict__ ea) {
    int e = blockIdx.x * 256 + threadIdx.x;
    if (e < Ee) {
        int dst = ei[Ee + e];
        atomicAdd(&g_deg[dst], 1);
        atomicAdd(&g_hist[dst * NTc + ea[e]], 1);
    }
}
__global__ void k_scan() {
    __shared__ int part[256];
    int tid = threadIdx.x;
    int base = tid * 32;
    int s = 0;
    for (int i = 0; i < 32; ++i) s += g_deg[base + i];
    part[tid] = s;
    __syncthreads();
    for (int off = 1; off < 256; off <<= 1) {
        int v = (tid >= off) ? part[tid - off] : 0;
        __syncthreads();
        part[tid] += v;
        __syncthreads();
    }
    int run = (tid == 0) ? 0 : part[tid - 1];
    for (int i = 0; i < 32; ++i) {
        int n = base + i;
        g_rowptr[n] = run;
        g_woff[n] = run;
        run += g_deg[n];
    }
    if (tid == 255) g_rowptr[Nn] = run;
}
__global__ void k_fill(const int* __restrict__ ei) {
    int e = blockIdx.x * 256 + threadIdx.x;
    if (e < Ee) {
        int dst = ei[Ee + e];
        int pos = atomicAdd(&g_woff[dst], 1);
        g_eid[pos] = e;
    }
}
__global__ void k_sort() {
    int n = blockIdx.x * 256 + threadIdx.x;
    if (n < Nn) {
        int r0 = g_rowptr[n], r1 = g_rowptr[n + 1];
        for (int i = r0 + 1; i < r1; ++i) {
            int v = g_eid[i];
            int j = i - 1;
            while (j >= r0 && g_eid[j] > v) { g_eid[j + 1] = g_eid[j]; --j; }
            g_eid[j + 1] = v;
        }
    }
}

// ---------------- fused packing: x, all weights, all tables ----------------
__global__ void __launch_bounds__(256)
k_pack_all(const float* __restrict__ x,
           const float* __restrict__ W_in,
           const float* __restrict__ Wl, const float* __restrict__ Wr,
           const float* __restrict__ W_out,
           const float* __restrict__ edge_emb, const float* __restrict__ We,
           __half* __restrict__ Apk, __half* __restrict__ Bpk) {
    const int bid = blockIdx.x;
    const int tid = threadIdx.x;

    if (bid < Nn) {
        const float4 v = *reinterpret_cast<const float4*>(x + (size_t)bid * DINc + tid * 4);
        __half h0 = __float2half_rn(v.x), h1 = __float2half_rn(v.y);
        __half h2 = __float2half_rn(v.z), h3 = __float2half_rn(v.w);
        __half2 hp0 = {h0, h1}, hp1 = {h2, h3};
        __half2 lp0 = {__float2half_rn(v.x - __half2float(h0)),
                       __float2half_rn(v.y - __half2float(h1))};
        __half2 lp1 = {__float2half_rn(v.z - __half2float(h2)),
                       __float2half_rn(v.w - __half2float(h3))};
        __half* p = Apk + (size_t)bid * 2 * DINc + tid * 4;
        reinterpret_cast<__half2*>(p)[0] = hp0;
        reinterpret_cast<__half2*>(p)[1] = hp1;
        reinterpret_cast<__half2*>(p + DINc)[0] = lp0;
        reinterpret_cast<__half2*>(p + DINc)[1] = lp1;
        return;
    }
    if (bid < Nn + 256 + 3072 + 64) {
        const float* W; __half* P; int K, N, nb, kb;
        int id = bid - Nn;
        if (id < 256) {
            W = W_in; P = Bpk + OFF_WIN; K = DINc; N = DHc;
            nb = id & 7; kb = id >> 3;
        } else if (id < 256 + 3072) {
            int id2 = id - 256;
            int mat = id2 >> 9;
            int t = id2 & 511;
            int l = mat >> 1, side = mat & 1;
            W = (side == 0 ? Wl : Wr) + (size_t)l * DHc * HDc;
            P = Bpk + OFF_WLR(l) + (size_t)side * HDc * 2 * DHc;
            K = DHc; N = HDc;
            nb = t & 63; kb = t >> 6;
        } else {
            int id2 = id - 256 - 3072;
            W = W_out; P = Bpk + OFF_WOUT; K = DHc; N = DHc;
            nb = id2 & 7; kb = id2 >> 3;
        }
        __shared__ float tbuf[32][33];
        int tx = tid & 31, ty = tid >> 5;
        #pragma unroll
        for (int i = 0; i < 32; i += 8)
            tbuf[ty + i][tx] = W[(size_t)(kb * 32 + ty + i) * N + nb * 32 + tx];
        __syncthreads();
        int K2 = 2 * K;
        #pragma unroll
        for (int i = 0; i < 32; i += 8) {
            int n = nb * 32 + ty + i;
            int k = kb * 32 + tx;
            __half hi = __float2half_rn(tbuf[tx][ty + i]);
            P[(size_t)n * K2 + k]     = hi;
            P[(size_t)n * K2 + K + k] = hi;
        }
        return;
    }
    {
        int id = bid - (Nn + 256 + 3072 + 64);
        int lt = id >> 3;
        int jb = id & 7;
        int l = lt / NTc, t = lt % NTc;
        int j = jb * 256 + tid;
        const float* w = We + (size_t)l * DHc * HDc + j;
        const float* e = edge_emb + t * DHc;
        float s = 0.f;
        #pragma unroll 4
        for (int k = 0; k < DHc; ++k) s = fmaf(e[k], w[(size_t)k * HDc], s);
        g_table[(size_t)l * NTc * HDc + t * HDc + j] = s;
    }
}

// ---------------- GEMM kernel 1 (proj): CTA 128x128, warp 32x64, 3-stage, 2 CTA/SM ----
#define GSTAGE 3
#define STG_BYTES 32768
#define GEMM_SMEM (GSTAGE * STG_BYTES)

__global__ void __launch_bounds__(256, 2)
k_gemm_mma(const __half* __restrict__ A, const __half* __restrict__ B,
           const float* __restrict__ bias, float* __restrict__ C, int Ktot, int Nc,
           const float* __restrict__ emb, const int* __restrict__ types,
           __half* __restrict__ packA) {
    extern __shared__ __align__(1024) char smem[];
    const uint32_t sb = smem_u32(smem);
    const int tid = threadIdx.x;
    const int lane = tid & 31, w = tid >> 5;
    const int wm = w & 3, wn = w >> 2;
    const int row0 = blockIdx.y * 128;
    const int col0 = blockIdx.x * 128;
    const int nch = Ktot >> 6;

    float acc[2][8][4];
    #pragma unroll
    for (int i = 0; i < 2; ++i)
        #pragma unroll
        for (int j = 0; j < 8; ++j)
            #pragma unroll
            for (int q = 0; q < 4; ++q) acc[i][j][q] = 0.f;

    uint32_t sm_off[4];
    const __half* gA[4];
    const __half* gB[4];
    #pragma unroll
    for (int u = 0; u < 4; ++u) {
        int i = tid + u * 256;
        int r = i >> 3, seg = i & 7;
        uint32_t off = (uint32_t)(r * 128 + seg * 16);
        sm_off[u] = off ^ ((off >> 3) & 0x70);
        gA[u] = A + (size_t)(row0 + r) * Ktot + (seg << 3);
        gB[u] = B + (size_t)(col0 + r) * Ktot + (seg << 3);
    }
    auto load_chunk = [&](int c) {
        const uint32_t s = sb + (uint32_t)((c % GSTAGE) * STG_BYTES);
        const int kof = c << 6;
        #pragma unroll
        for (int u = 0; u < 4; ++u) cp16(s + sm_off[u], gA[u] + kof);
        #pragma unroll
        for (int u = 0; u < 4; ++u) cp16(s + 16384 + sm_off[u], gB[u] + kof);
        asm volatile("cp.async.commit_group;");
    };
    #pragma unroll
    for (int c = 0; c < GSTAGE - 1; ++c) load_chunk(c);

    uint32_t a_base[2], a_swz[2];
    #pragma unroll
    for (int mb = 0; mb < 2; ++mb) {
        int row = wm * 32 + mb * 16 + (lane & 15);
        a_base[mb] = (uint32_t)(row * 128 + ((lane >> 4) << 4));
        a_swz[mb] = (uint32_t)((row & 7) << 4);
    }
    uint32_t b_base[4], b_swz[4];
    #pragma unroll
    for (int nb = 0; nb < 4; ++nb) {
        int row = wn * 64 + nb * 16 + (lane & 7) + ((lane >> 4) << 3);
        b_base[nb] = (uint32_t)(row * 128 + (((lane >> 3) & 1) << 4));
        b_swz[nb] = (uint32_t)((row & 7) << 4);
    }

    for (int c = 0; c < nch; ++c) {
        asm volatile("cp.async.wait_group %0;" :: "n"(GSTAGE - 2));
        __syncthreads();
        if (c + GSTAGE - 1 < nch) load_chunk(c + GSTAGE - 1);
        else asm volatile("cp.async.commit_group;");
        const uint32_t stb = sb + (uint32_t)((c % GSTAGE) * STG_BYTES);
        #pragma unroll
        for (int kk = 0; kk < 4; ++kk) {
            const uint32_t kby = (uint32_t)(kk * 32);
            uint32_t a[2][4];
            #pragma unroll
            for (int mb = 0; mb < 2; ++mb)
                ldsm_x4(a[mb], stb + ((a_base[mb] + kby) ^ a_swz[mb]));
            uint32_t b[4][4];
            #pragma unroll
            for (int nb = 0; nb < 4; ++nb)
                ldsm_x4(b[nb], stb + 16384 + ((b_base[nb] + kby) ^ b_swz[nb]));
            #pragma unroll
            for (int mb = 0; mb < 2; ++mb)
                #pragma unroll
                for (int nb = 0; nb < 4; ++nb) {
                    mma_f16(acc[mb][2 * nb],     a[mb], b[nb][0], b[nb][1]);
                    mma_f16(acc[mb][2 * nb + 1], a[mb], b[nb][2], b[nb][3]);
                }
        }
    }

    const int r_base = row0 + wm * 32 + (lane >> 2);
    const int c_base = col0 + wn * 64 + ((lane & 3) << 1);
    const int K2 = 2 * Nc;
    #pragma unroll
    for (int mb = 0; mb < 2; ++mb) {
        const int r1 = r_base + mb * 16;
        const int r2 = r1 + 8;
        #pragma unroll
        for (int nt = 0; nt < 8; ++nt) {
            const int col = c_base + nt * 8;
            float bx = bias[col], by = bias[col + 1];
            float e1x = 0.f, e1y = 0.f, e2x = 0.f, e2y = 0.f;
            if (emb) {
                const float* em1 = emb + (size_t)types[r1] * Nc + col;
                const float* em2 = emb + (size_t)types[r2] * Nc + col;
                e1x = em1[0]; e1y = em1[1]; e2x = em2[0]; e2y = em2[1];
            }
            float v00 = acc[mb][nt][0] + bx + e1x;
            float v01 = acc[mb][nt][1] + by + e1y;
            float v10 = acc[mb][nt][2] + bx + e2x;
            float v11 = acc[mb][nt][3] + by + e2y;
            if (C) {
                float2 t0 = {v00, v01}, t1 = {v10, v11};
                *reinterpret_cast<float2*>(&C[(size_t)r1 * Nc + col]) = t0;
                *reinterpret_cast<float2*>(&C[(size_t)r2 * Nc + col]) = t1;
            }
            if (packA) {
                __half h00 = __float2half_rn(v00);
                __half h01 = __float2half_rn(v01);
                __half h10 = __float2half_rn(v10);
                __half h11 = __float2half_rn(v11);
                __half2 hp1 = {h00, h01};
                __half2 hp2 = {h10, h11};
                __half2 lp1 = {__float2half_rn(v00 - __half2float(h00)),
                               __float2half_rn(v01 - __half2float(h01))};
                __half2 lp2 = {__float2half_rn(v10 - __half2float(h10)),
                               __float2half_rn(v11 - __half2float(h11))};
                __half* p1 = packA + (size_t)r1 * K2 + col;
                __half* p2 = packA + (size_t)r2 * K2 + col;
                *reinterpret_cast<__half2*>(p1)      = hp1;
                *reinterpret_cast<__half2*>(p1 + Nc) = lp1;
                *reinterpret_cast<__half2*>(p2)      = hp2;
                *reinterpret_cast<__half2*>(p2 + Nc) = lp2;
            }
        }
    }
}

// ---------------- GEMM kernel 2 (merged xl|xr): CTA 128x256, warp 64x64, 4-stage ----
#define BGSTAGE 4
#define BSTG_BYTES 49152
#define BGEMM_SMEM (BGSTAGE * BSTG_BYTES)

__global__ void __launch_bounds__(256, 1)
k_gemm_big(const __half* __restrict__ A, const __half* __restrict__ B,
           const float* __restrict__ bias, const float* __restrict__ bias2, int halfN,
           __half* __restrict__ C, int Ktot, int Nc) {
    extern __shared__ __align__(1024) char smem[];
    const uint32_t sb = smem_u32(smem);
    const int tid = threadIdx.x;
    const int lane = tid & 31, w = tid >> 5;
    const int wm = w & 1, wn = w >> 1;
    const int row0 = blockIdx.y * 128;
    const int col0 = blockIdx.x * 256;
    const int nch = Ktot >> 6;

    float acc[4][8][4];
    #pragma unroll
    for (int i = 0; i < 4; ++i)
        #pragma unroll
        for (int j = 0; j < 8; ++j)
            #pragma unroll
            for (int q = 0; q < 4; ++q) acc[i][j][q] = 0.f;

    uint32_t sm_offA[4], sm_offB[8];
    const __half* gA[4];
    const __half* gB[8];
    #pragma unroll
    for (int u = 0; u < 4; ++u) {
        int i = tid + u * 256;
        int r = i >> 3, seg = i & 7;
        uint32_t off = (uint32_t)(r * 128 + seg * 16);
        sm_offA[u] = off ^ ((off >> 3) & 0x70);
        gA[u] = A + (size_t)(row0 + r) * Ktot + (seg << 3);
    }
    #pragma unroll
    for (int u = 0; u < 8; ++u) {
        int i = tid + u * 256;
        int r = i >> 3, seg = i & 7;
        uint32_t off = (uint32_t)(r * 128 + seg * 16);
        sm_offB[u] = off ^ ((off >> 3) & 0x70);
        gB[u] = B + (size_t)(col0 + r) * Ktot + (seg << 3);
    }
    auto load_chunk = [&](int c) {
        const uint32_t s = sb + (uint32_t)((c % BGSTAGE) * BSTG_BYTES);
        const int kof = c << 6;
        #pragma unroll
        for (int u = 0; u < 4; ++u) cp16(s + sm_offA[u], gA[u] + kof);
        #pragma unroll
        for (int u = 0; u < 8; ++u) cp16(s + 16384 + sm_offB[u], gB[u] + kof);
        asm volatile("cp.async.commit_group;");
    };
    #pragma unroll
    for (int c = 0; c < BGSTAGE - 1; ++c) load_chunk(c);

    uint32_t a_base[4], a_swz[4];
    #pragma unroll
    for (int mb = 0; mb < 4; ++mb) {
        int row = wm * 64 + mb * 16 + (lane & 15);
        a_base[mb] = (uint32_t)(row * 128 + ((lane >> 4) << 4));
        a_swz[mb] = (uint32_t)((row & 7) << 4);
    }
    uint32_t b_base[4], b_swz[4];
    #pragma unroll
    for (int nb = 0; nb < 4; ++nb) {
        int row = wn * 64 + nb * 16 + (lane & 7) + ((lane >> 4) << 3);
        b_base[nb] = (uint32_t)(row * 128 + (((lane >> 3) & 1) << 4));
        b_swz[nb] = (uint32_t)((row & 7) << 4);
    }

    for (int c = 0; c < nch; ++c) {
        asm volatile("cp.async.wait_group %0;" :: "n"(BGSTAGE - 2));
        __syncthreads();
        if (c + BGSTAGE - 1 < nch) load_chunk(c + BGSTAGE - 1);
        else asm volatile("cp.async.commit_group;");
        const uint32_t stb = sb + (uint32_t)((c % BGSTAGE) * BSTG_BYTES);
        #pragma unroll
        for (int kk = 0; kk < 4; ++kk) {
            const uint32_t kby = (uint32_t)(kk * 32);
            uint32_t a[4][4];
            #pragma unroll
            for (int mb = 0; mb < 4; ++mb)
                ldsm_x4(a[mb], stb + ((a_base[mb] + kby) ^ a_swz[mb]));
            uint32_t b[4][4];
            #pragma unroll
            for (int nb = 0; nb < 4; ++nb)
                ldsm_x4(b[nb], stb + 16384 + ((b_base[nb] + kby) ^ b_swz[nb]));
            #pragma unroll
            for (int mb = 0; mb < 4; ++mb)
                #pragma unroll
                for (int nb = 0; nb < 4; ++nb) {
                    mma_f16(acc[mb][2 * nb],     a[mb], b[nb][0], b[nb][1]);
                    mma_f16(acc[mb][2 * nb + 1], a[mb], b[nb][2], b[nb][3]);
                }
        }
    }

    const float* bp = bias;
    int cadj = 0;
    if (bias2 && col0 >= halfN) { bp = bias2; cadj = halfN; }
    const int r_base = row0 + wm * 64 + (lane >> 2);
    const int c_base = col0 + wn * 64 + ((lane & 3) << 1);
    #pragma unroll
    for (int mb = 0; mb < 4; ++mb) {
        const int r1 = r_base + mb * 16;
        const int r2 = r1 + 8;
        #pragma unroll
        for (int nt = 0; nt < 8; ++nt) {
            const int col = c_base + nt * 8;
            float bx = bp[col - cadj], by = bp[col + 1 - cadj];
            __half2 t0 = __floats2half2_rn(acc[mb][nt][0] + bx, acc[mb][nt][1] + by);
            __half2 t1 = __floats2half2_rn(acc[mb][nt][2] + bx, acc[mb][nt][3] + by);
            *reinterpret_cast<__half2*>(&C[(size_t)r1 * Nc + col]) = t0;
            *reinterpret_cast<__half2*>(&C[(size_t)r2 * Nc + col]) = t1;
        }
    }
}

// ---------------- fused GATv2 edge kernel: 8 nodes/block, table+att in smem ----------
// dynamic smem: att[2048] | tab[5*2048] | xr[2048] | lee[2048] | out[2048]  (fp32, 72KB)
#define EDGE_SMEM (9 * HDc * 4)

__global__ void __launch_bounds__(256)
k_edge(const int* __restrict__ edge_index, const int* __restrict__ edge_attr,
       const float* __restrict__ att_l, const float* __restrict__ bgat_l,
       int loff, __half* __restrict__ packH) {
    extern __shared__ float sm[];
    float* s_att = sm;
    float* s_tab = sm + HDc;
    float* s_xr  = sm + 6 * HDc;
    float* s_lee = sm + 7 * HDc;
    float* s_out = sm + 8 * HDc;

    const int tid = threadIdx.x;
    const int lane = tid & 31;
    const int base = ((tid >> 5) << 8) + (lane << 3);

    // preamble once per block: att + full 5-type table into smem
    const float* tb = g_table + loff;
    #pragma unroll
    for (int u = 0; u < 8; ++u) s_att[tid + u * 256] = att_l[tid + u * 256];
    #pragma unroll
    for (int u = 0; u < 40; ++u) s_tab[tid + u * 256] = tb[tid + u * 256];
    __syncthreads();

    for (int g = 0; g < EGc; ++g) {
        const int n = blockIdx.x * EGc + g;
        const int r0 = g_rowptr[n], r1 = g_rowptr[n + 1];
        const int deg = r1 - r0;
        const float inv = 1.0f / (float)(deg > 1 ? deg : 1);

        float c0 = (float)g_hist[n * NTc + 0];
        float c1 = (float)g_hist[n * NTc + 1];
        float c2 = (float)g_hist[n * NTc + 2];
        float c3 = (float)g_hist[n * NTc + 3];
        float c4 = (float)g_hist[n * NTc + 4];

        // load xr (fp16 -> fp32 smem) and compute lee from smem table
        {
            int j8 = tid * 8;
            uint4 raw = *reinterpret_cast<const uint4*>(g_xlr + (size_t)n * N2c + HDc + j8);
            __half2 p0 = *reinterpret_cast<__half2*>(&raw.x);
            __half2 p1 = *reinterpret_cast<__half2*>(&raw.y);
            __half2 p2 = *reinterpret_cast<__half2*>(&raw.z);
            __half2 p3 = *reinterpret_cast<__half2*>(&raw.w);
            s_xr[j8 + 0] = __half2float(p0.x); s_xr[j8 + 1] = __half2float(p0.y);
            s_xr[j8 + 2] = __half2float(p1.x); s_xr[j8 + 3] = __half2float(p1.y);
            s_xr[j8 + 4] = __half2float(p2.x); s_xr[j8 + 5] = __half2float(p2.y);
            s_xr[j8 + 6] = __half2float(p3.x); s_xr[j8 + 7] = __half2float(p3.y);
        }
        #pragma unroll
        for (int u = 0; u < 8; ++u) {
            int j = tid + u * 256;
            float v = c0 * s_tab[0 * HDc + j];
            v = fmaf(c1, s_tab[1 * HDc + j], v);
            v = fmaf(c2, s_tab[2 * HDc + j], v);
            v = fmaf(c3, s_tab[3 * HDc + j], v);
            v = fmaf(c4, s_tab[4 * HDc + j], v);
            s_lee[j] = v * inv;
        }
        __syncthreads();

        float m = -1e30f, d = 0.f;
        float acc[8];
        #pragma unroll
        for (int i = 0; i < 8; ++i) acc[i] = 0.f;

        int s_cur = n, t_cur = -1;
        if (r0 < r1) {
            int e = g_eid[r0];
            s_cur = edge_index[e];
            t_cur = edge_attr[e];
        }
        for (int idx = r0; idx <= r1; ++idx) {
            const bool isloop = (idx == r1);
            uint4 raw = *reinterpret_cast<const uint4*>(g_xlr + (size_t)s_cur * N2c + base);
            int s_nxt = n, t_nxt = -1;
            if (idx + 1 < r1) {
                int e = g_eid[idx + 1];
                s_nxt = edge_index[e];
                t_nxt = edge_attr[e];
            }
            __half2 p0 = *reinterpret_cast<__half2*>(&raw.x);
            __half2 p1 = *reinterpret_cast<__half2*>(&raw.y);
            __half2 p2 = *reinterpret_cast<__half2*>(&raw.z);
            __half2 p3 = *reinterpret_cast<__half2*>(&raw.w);
            float xlv[8];
            xlv[0] = __half2float(p0.x); xlv[1] = __half2float(p0.y);
            xlv[2] = __half2float(p1.x); xlv[3] = __half2float(p1.y);
            xlv[4] = __half2float(p2.x); xlv[5] = __half2float(p2.y);
            xlv[6] = __half2float(p3.x); xlv[7] = __half2float(p3.y);

            const float* tab = isloop ? (s_lee + base) : (s_tab + t_cur * HDc + base);
            float part = 0.f;
            #pragma unroll
            for (int i = 0; i < 8; ++i) {
                float z = xlv[i] + s_xr[base + i] + tab[i];
                z = z > 0.f ? z : 0.2f * z;
                part = fmaf(z, s_att[base + i], part);
            }
            #pragma unroll
            for (int o = 16; o > 0; o >>= 1)
                part += __shfl_xor_sync(0xffffffffu, part, o);

            float mn = fmaxf(m, part);
            float sc = __expf(m - mn);
            float p  = __expf(part - mn);
            d = d * sc + p;
            #pragma unroll
            for (int i = 0; i < 8; ++i) acc[i] = fmaf(acc[i], sc, p * xlv[i]);
            m = mn;
            s_cur = s_nxt; t_cur = t_nxt;
        }

        float invd = 1.0f / d;
        #pragma unroll
        for (int i = 0; i < 8; ++i) s_out[base + i] = acc[i] * invd;
        __syncthreads();

        {
            int c = tid;
            float v = 0.f;
            #pragma unroll
            for (int h = 0; h < HHc; ++h) v += s_out[h * DHc + c];
            v = fmaf(v, 0.125f, bgat_l[c]);
            v = fmaxf(v, 0.f);
            __half hi = __float2half_rn(v);
            __half lo = __float2half_rn(v - __half2float(hi));
            __half* p = packH + (size_t)n * (2 * DHc) + c;
            p[0]   = hi;
            p[DHc] = lo;
        }
        __syncthreads();   // before s_xr/s_lee/s_out reuse
    }
}

// ---------------- host orchestration ----------------
extern "C" void kernel_launch(void* const* d_in, const int* in_sizes, int n_in,
                              void* d_out, int out_size) {
    const float* x         = (const float*)d_in[0];
    const int*   edge_index= (const int*)  d_in[1];
    const int*   edge_attr = (const int*)  d_in[2];
    const int*   node_types= (const int*)  d_in[3];
    const float* W_in      = (const float*)d_in[4];
    const float* b_in      = (const float*)d_in[5];
    const float* node_emb  = (const float*)d_in[6];
    const float* edge_emb  = (const float*)d_in[7];
    const float* Wl        = (const float*)d_in[8];
    const float* bl        = (const float*)d_in[9];
    const float* Wr        = (const float*)d_in[10];
    const float* br        = (const float*)d_in[11];
    const float* We        = (const float*)d_in[12];
    const float* att       = (const float*)d_in[13];
    const float* b_gat     = (const float*)d_in[14];
    const float* W_out     = (const float*)d_in[15];
    const float* b_out     = (const float*)d_in[16];
    float* out = (float*)d_out;

    __half* xlr;    cudaGetSymbolAddress((void**)&xlr, g_xlr);
    __half* Apk;    cudaGetSymbolAddress((void**)&Apk, g_Apack);
    __half* Hpk;    cudaGetSymbolAddress((void**)&Hpk, g_hpack);
    __half* Bpk;    cudaGetSymbolAddress((void**)&Bpk, g_Bpack);

    cudaFuncSetAttribute(k_gemm_mma, cudaFuncAttributeMaxDynamicSharedMemorySize, GEMM_SMEM);
    cudaFuncSetAttribute(k_gemm_big, cudaFuncAttributeMaxDynamicSharedMemorySize, BGEMM_SMEM);
    cudaFuncSetAttribute(k_edge, cudaFuncAttributeMaxDynamicSharedMemorySize, EDGE_SMEM);

    // 1: pack everything
    k_pack_all<<<Nn + 256 + 3072 + 64 + 120, 256>>>(x, W_in, Wl, Wr, W_out,
                                                    edge_emb, We, Apk, Bpk);
    // 2: CSR zero
    k_zero<<<(Nn * NTc + 255) / 256, 256>>>();
    // 3: input projection -> packed h0
    k_gemm_mma<<<dim3(2, 64), 256, GEMM_SMEM>>>(
        Apk, Bpk + OFF_WIN, b_in, nullptr, 2 * DINc, DHc, node_emb, node_types, Hpk);
    // 4: merged xl|xr GEMM layer 0   <- ncu capture slot
    k_gemm_big<<<dim3(N2c / 256, 64), 256, BGEMM_SMEM>>>(
        Hpk, Bpk + OFF_WLR(0), bl, br, HDc, xlr, 2 * DHc, N2c);
    // 5-8: finish CSR
    k_count<<<(Ee + 255) / 256, 256>>>(edge_index, edge_attr);
    k_scan<<<1, 256>>>();
    k_fill<<<(Ee + 255) / 256, 256>>>(edge_index);
    k_sort<<<(Nn + 255) / 256, 256>>>();

    for (int l = 0; l < LLc; ++l) {
        if (l > 0) {
            k_gemm_big<<<dim3(N2c / 256, 64), 256, BGEMM_SMEM>>>(
                Hpk, Bpk + OFF_WLR(l), bl + (size_t)l * HDc, br + (size_t)l * HDc,
                HDc, xlr, 2 * DHc, N2c);
        }
        k_edge<<<Nn / EGc, 256, EDGE_SMEM>>>(edge_index, edge_attr,
                                             att + (size_t)l * HHc * DHc,
                                             b_gat + (size_t)l * DHc,
                                             l * NTc * HDc, Hpk);
    }

    // output projection -> d_out fp32
    k_gemm_mma<<<dim3(2, 64), 256, GEMM_SMEM>>>(
        Hpk, Bpk + OFF_WOUT, b_out, out, 2 * DHc, DHc, nullptr, nullptr, nullptr);

    (void)in_sizes; (void)n_in; (void)out_size;
}

// round 10
// speedup vs baseline: 2.2940x; 1.2193x over previous
#include <cuda_runtime.h>
#include <cuda_fp16.h>
#include <math.h>
#include <stdint.h>

// Problem constants
#define Nn   8192
#define Ee   32768
#define DINc 1024
#define DHc  256
#define HHc  8
#define LLc  3
#define HDc  2048   // H*DH
#define NTc  5
#define N2c  4096   // merged Wl|Wr output width
#define EGc  8      // nodes per edge-kernel block

// ---------------- device scratch ----------------
__device__ __half g_xlr[(size_t)Nn * N2c];         // merged xl|xr, fp16 (L2-resident)
__device__ float g_table[LLc * NTc * HDc];
__device__ int   g_deg[Nn];
__device__ int   g_hist[Nn * NTc];
__device__ int   g_rowptr[Nn + 1];
__device__ int   g_woff[Nn];
__device__ int   g_eid[Ee];

// Apack/hpack: [Ah|Al] fp16x2 (2K). Wl/Wr packed SINGLE-copy (K=256); W_in/W_out dup (2K).
__device__ __half g_Apack[(size_t)Nn * 2 * DINc];
__device__ __half g_hpack[(size_t)Nn * 2 * DHc];
__device__ __half g_Bpack[7000000];

#define OFF_WIN  0
#define SZ_WIN   (DHc * 2 * DINc)                 // 524288
#define SZ_L     ((size_t)N2c * DHc)              // 1048576 (single-copy Wl|Wr)
#define OFF_WLR(l) (SZ_WIN + (size_t)(l) * SZ_L)
#define OFF_WOUT (SZ_WIN + (size_t)3 * SZ_L)

// ---------------- PTX helpers ----------------
__device__ __forceinline__ uint32_t smem_u32(const void* p) {
    uint32_t a;
    asm("{ .reg .u64 t; cvta.to.shared.u64 t, %1; cvt.u32.u64 %0, t; }" : "=r"(a) : "l"(p));
    return a;
}
__device__ __forceinline__ void cp16(uint32_t d, const void* g) {
    asm volatile("cp.async.cg.shared.global [%0], [%1], 16;" :: "r"(d), "l"(g));
}
__device__ __forceinline__ void ldsm_x4(uint32_t* r, uint32_t addr) {
    asm volatile("ldmatrix.sync.aligned.m8n8.x4.shared.b16 {%0,%1,%2,%3}, [%4];"
                 : "=r"(r[0]), "=r"(r[1]), "=r"(r[2]), "=r"(r[3]) : "r"(addr));
}
__device__ __forceinline__ void mma_f16(float* c, const uint32_t* a, uint32_t b0, uint32_t b1) {
    asm volatile(
        "mma.sync.aligned.m16n8k16.row.col.f32.f16.f16.f32 "
        "{%0,%1,%2,%3}, {%4,%5,%6,%7}, {%8,%9}, {%0,%1,%2,%3};"
        : "+f"(c[0]), "+f"(c[1]), "+f"(c[2]), "+f"(c[3])
        : "r"(a[0]), "r"(a[1]), "r"(a[2]), "r"(a[3]), "r"(b0), "r"(b1));
}

// ---------------- CSR build ----------------
__global__ void k_zero() {
    int i = blockIdx.x * 256 + threadIdx.x;
    if (i < Nn) g_deg[i] = 0;
    if (i < Nn * NTc) g_hist[i] = 0;
}
__global__ void k_count(const int* __restrict__ ei, const int* __restrict__ ea) {
    int e = blockIdx.x * 256 + threadIdx.x;
    if (e < Ee) {
        int dst = ei[Ee + e];
        atomicAdd(&g_deg[dst], 1);
        atomicAdd(&g_hist[dst * NTc + ea[e]], 1);
    }
}
__global__ void k_scan() {
    __shared__ int part[256];
    int tid = threadIdx.x;
    int base = tid * 32;
    int s = 0;
    for (int i = 0; i < 32; ++i) s += g_deg[base + i];
    part[tid] = s;
    __syncthreads();
    for (int off = 1; off < 256; off <<= 1) {
        int v = (tid >= off) ? part[tid - off] : 0;
        __syncthreads();
        part[tid] += v;
        __syncthreads();
    }
    int run = (tid == 0) ? 0 : part[tid - 1];
    for (int i = 0; i < 32; ++i) {
        int n = base + i;
        g_rowptr[n] = run;
        g_woff[n] = run;
        run += g_deg[n];
    }
    if (tid == 255) g_rowptr[Nn] = run;
}
__global__ void k_fill(const int* __restrict__ ei) {
    int e = blockIdx.x * 256 + threadIdx.x;
    if (e < Ee) {
        int dst = ei[Ee + e];
        int pos = atomicAdd(&g_woff[dst], 1);
        g_eid[pos] = e;
    }
}
__global__ void k_sort() {
    int n = blockIdx.x * 256 + threadIdx.x;
    if (n < Nn) {
        int r0 = g_rowptr[n], r1 = g_rowptr[n + 1];
        for (int i = r0 + 1; i < r1; ++i) {
            int v = g_eid[i];
            int j = i - 1;
            while (j >= r0 && g_eid[j] > v) { g_eid[j + 1] = g_eid[j]; --j; }
            g_eid[j + 1] = v;
        }
    }
}

// ---------------- fused packing: x, all weights, all tables ----------------
__global__ void __launch_bounds__(256)
k_pack_all(const float* __restrict__ x,
           const float* __restrict__ W_in,
           const float* __restrict__ Wl, const float* __restrict__ Wr,
           const float* __restrict__ W_out,
           const float* __restrict__ edge_emb, const float* __restrict__ We,
           __half* __restrict__ Apk, __half* __restrict__ Bpk) {
    const int bid = blockIdx.x;
    const int tid = threadIdx.x;

    if (bid < Nn) {
        const float4 v = *reinterpret_cast<const float4*>(x + (size_t)bid * DINc + tid * 4);
        __half h0 = __float2half_rn(v.x), h1 = __float2half_rn(v.y);
        __half h2 = __float2half_rn(v.z), h3 = __float2half_rn(v.w);
        __half2 hp0 = {h0, h1}, hp1 = {h2, h3};
        __half2 lp0 = {__float2half_rn(v.x - __half2float(h0)),
                       __float2half_rn(v.y - __half2float(h1))};
        __half2 lp1 = {__float2half_rn(v.z - __half2float(h2)),
                       __float2half_rn(v.w - __half2float(h3))};
        __half* p = Apk + (size_t)bid * 2 * DINc + tid * 4;
        reinterpret_cast<__half2*>(p)[0] = hp0;
        reinterpret_cast<__half2*>(p)[1] = hp1;
        reinterpret_cast<__half2*>(p + DINc)[0] = lp0;
        reinterpret_cast<__half2*>(p + DINc)[1] = lp1;
        return;
    }
    if (bid < Nn + 256 + 3072 + 64) {
        const float* W; __half* P; int K, N, nb, kb;
        bool dup;
        int id = bid - Nn;
        if (id < 256) {
            W = W_in; P = Bpk + OFF_WIN; K = DINc; N = DHc; dup = true;
            nb = id & 7; kb = id >> 3;
        } else if (id < 256 + 3072) {
            int id2 = id - 256;
            int mat = id2 >> 9;
            int t = id2 & 511;
            int l = mat >> 1, side = mat & 1;
            W = (side == 0 ? Wl : Wr) + (size_t)l * DHc * HDc;
            P = Bpk + OFF_WLR(l) + (size_t)side * HDc * DHc;
            K = DHc; N = HDc; dup = false;
            nb = t & 63; kb = t >> 6;
        } else {
            int id2 = id - 256 - 3072;
            W = W_out; P = Bpk + OFF_WOUT; K = DHc; N = DHc; dup = true;
            nb = id2 & 7; kb = id2 >> 3;
        }
        __shared__ float tbuf[32][33];
        int tx = tid & 31, ty = tid >> 5;
        #pragma unroll
        for (int i = 0; i < 32; i += 8)
            tbuf[ty + i][tx] = W[(size_t)(kb * 32 + ty + i) * N + nb * 32 + tx];
        __syncthreads();
        const int stride = dup ? 2 * K : K;
        #pragma unroll
        for (int i = 0; i < 32; i += 8) {
            int n = nb * 32 + ty + i;
            int k = kb * 32 + tx;
            __half hi = __float2half_rn(tbuf[tx][ty + i]);
            P[(size_t)n * stride + k] = hi;
            if (dup) P[(size_t)n * stride + K + k] = hi;
        }
        return;
    }
    {
        int id = bid - (Nn + 256 + 3072 + 64);
        int lt = id >> 3;
        int jb = id & 7;
        int l = lt / NTc, t = lt % NTc;
        int j = jb * 256 + tid;
        const float* w = We + (size_t)l * DHc * HDc + j;
        const float* e = edge_emb + t * DHc;
        float s = 0.f;
        #pragma unroll 4
        for (int k = 0; k < DHc; ++k) s = fmaf(e[k], w[(size_t)k * HDc], s);
        g_table[(size_t)l * NTc * HDc + t * HDc + j] = s;
    }
}

// ---------------- GEMM kernel 1 (proj): CTA 128x128, warp 32x64, 3-stage, 2 CTA/SM ----
#define GSTAGE 3
#define STG_BYTES 32768
#define GEMM_SMEM (GSTAGE * STG_BYTES)

__global__ void __launch_bounds__(256, 2)
k_gemm_mma(const __half* __restrict__ A, const __half* __restrict__ B,
           const float* __restrict__ bias, float* __restrict__ C, int Ktot, int Nc,
           const float* __restrict__ emb, const int* __restrict__ types,
           __half* __restrict__ packA) {
    extern __shared__ __align__(1024) char smem[];
    const uint32_t sb = smem_u32(smem);
    const int tid = threadIdx.x;
    const int lane = tid & 31, w = tid >> 5;
    const int wm = w & 3, wn = w >> 2;
    const int row0 = blockIdx.y * 128;
    const int col0 = blockIdx.x * 128;
    const int nch = Ktot >> 6;

    float acc[2][8][4];
    #pragma unroll
    for (int i = 0; i < 2; ++i)
        #pragma unroll
        for (int j = 0; j < 8; ++j)
            #pragma unroll
            for (int q = 0; q < 4; ++q) acc[i][j][q] = 0.f;

    uint32_t sm_off[4];
    const __half* gA[4];
    const __half* gB[4];
    #pragma unroll
    for (int u = 0; u < 4; ++u) {
        int i = tid + u * 256;
        int r = i >> 3, seg = i & 7;
        uint32_t off = (uint32_t)(r * 128 + seg * 16);
        sm_off[u] = off ^ ((off >> 3) & 0x70);
        gA[u] = A + (size_t)(row0 + r) * Ktot + (seg << 3);
        gB[u] = B + (size_t)(col0 + r) * Ktot + (seg << 3);
    }
    auto load_chunk = [&](int c) {
        const uint32_t s = sb + (uint32_t)((c % GSTAGE) * STG_BYTES);
        const int kof = c << 6;
        #pragma unroll
        for (int u = 0; u < 4; ++u) cp16(s + sm_off[u], gA[u] + kof);
        #pragma unroll
        for (int u = 0; u < 4; ++u) cp16(s + 16384 + sm_off[u], gB[u] + kof);
        asm volatile("cp.async.commit_group;");
    };
    #pragma unroll
    for (int c = 0; c < GSTAGE - 1; ++c) load_chunk(c);

    uint32_t a_base[2], a_swz[2];
    #pragma unroll
    for (int mb = 0; mb < 2; ++mb) {
        int row = wm * 32 + mb * 16 + (lane & 15);
        a_base[mb] = (uint32_t)(row * 128 + ((lane >> 4) << 4));
        a_swz[mb] = (uint32_t)((row & 7) << 4);
    }
    uint32_t b_base[4], b_swz[4];
    #pragma unroll
    for (int nb = 0; nb < 4; ++nb) {
        int row = wn * 64 + nb * 16 + (lane & 7) + ((lane >> 4) << 3);
        b_base[nb] = (uint32_t)(row * 128 + (((lane >> 3) & 1) << 4));
        b_swz[nb] = (uint32_t)((row & 7) << 4);
    }

    for (int c = 0; c < nch; ++c) {
        asm volatile("cp.async.wait_group %0;" :: "n"(GSTAGE - 2));
        __syncthreads();
        if (c + GSTAGE - 1 < nch) load_chunk(c + GSTAGE - 1);
        else asm volatile("cp.async.commit_group;");
        const uint32_t stb = sb + (uint32_t)((c % GSTAGE) * STG_BYTES);
        #pragma unroll
        for (int kk = 0; kk < 4; ++kk) {
            const uint32_t kby = (uint32_t)(kk * 32);
            uint32_t a[2][4];
            #pragma unroll
            for (int mb = 0; mb < 2; ++mb)
                ldsm_x4(a[mb], stb + ((a_base[mb] + kby) ^ a_swz[mb]));
            uint32_t b[4][4];
            #pragma unroll
            for (int nb = 0; nb < 4; ++nb)
                ldsm_x4(b[nb], stb + 16384 + ((b_base[nb] + kby) ^ b_swz[nb]));
            #pragma unroll
            for (int mb = 0; mb < 2; ++mb)
                #pragma unroll
                for (int nb = 0; nb < 4; ++nb) {
                    mma_f16(acc[mb][2 * nb],     a[mb], b[nb][0], b[nb][1]);
                    mma_f16(acc[mb][2 * nb + 1], a[mb], b[nb][2], b[nb][3]);
                }
        }
    }

    const int r_base = row0 + wm * 32 + (lane >> 2);
    const int c_base = col0 + wn * 64 + ((lane & 3) << 1);
    const int K2 = 2 * Nc;
    #pragma unroll
    for (int mb = 0; mb < 2; ++mb) {
        const int r1 = r_base + mb * 16;
        const int r2 = r1 + 8;
        #pragma unroll
        for (int nt = 0; nt < 8; ++nt) {
            const int col = c_base + nt * 8;
            float bx = bias[col], by = bias[col + 1];
            float e1x = 0.f, e1y = 0.f, e2x = 0.f, e2y = 0.f;
            if (emb) {
                const float* em1 = emb + (size_t)types[r1] * Nc + col;
                const float* em2 = emb + (size_t)types[r2] * Nc + col;
                e1x = em1[0]; e1y = em1[1]; e2x = em2[0]; e2y = em2[1];
            }
            float v00 = acc[mb][nt][0] + bx + e1x;
            float v01 = acc[mb][nt][1] + by + e1y;
            float v10 = acc[mb][nt][2] + bx + e2x;
            float v11 = acc[mb][nt][3] + by + e2y;
            if (C) {
                float2 t0 = {v00, v01}, t1 = {v10, v11};
                *reinterpret_cast<float2*>(&C[(size_t)r1 * Nc + col]) = t0;
                *reinterpret_cast<float2*>(&C[(size_t)r2 * Nc + col]) = t1;
            }
            if (packA) {
                __half h00 = __float2half_rn(v00);
                __half h01 = __float2half_rn(v01);
                __half h10 = __float2half_rn(v10);
                __half h11 = __float2half_rn(v11);
                __half2 hp1 = {h00, h01};
                __half2 hp2 = {h10, h11};
                __half2 lp1 = {__float2half_rn(v00 - __half2float(h00)),
                               __float2half_rn(v01 - __half2float(h01))};
                __half2 lp2 = {__float2half_rn(v10 - __half2float(h10)),
                               __float2half_rn(v11 - __half2float(h11))};
                __half* p1 = packA + (size_t)r1 * K2 + col;
                __half* p2 = packA + (size_t)r2 * K2 + col;
                *reinterpret_cast<__half2*>(p1)      = hp1;
                *reinterpret_cast<__half2*>(p1 + Nc) = lp1;
                *reinterpret_cast<__half2*>(p2)      = hp2;
                *reinterpret_cast<__half2*>(p2 + Nc) = lp2;
            }
        }
    }
}

// ---------------- GEMM kernel 2 (merged xl|xr): CTA 128x256, warp 64x64, 4-stage ----
// A has row stride lda (elements); K-extent Ktot.
#define BGSTAGE 4
#define BSTG_BYTES 49152
#define BGEMM_SMEM (BGSTAGE * BSTG_BYTES)

__global__ void __launch_bounds__(256, 1)
k_gemm_big(const __half* __restrict__ A, int lda, const __half* __restrict__ B,
           const float* __restrict__ bias, const float* __restrict__ bias2, int halfN,
           __half* __restrict__ C, int Ktot, int Nc) {
    extern __shared__ __align__(1024) char smem[];
    const uint32_t sb = smem_u32(smem);
    const int tid = threadIdx.x;
    const int lane = tid & 31, w = tid >> 5;
    const int wm = w & 1, wn = w >> 1;
    const int row0 = blockIdx.y * 128;
    const int col0 = blockIdx.x * 256;
    const int nch = Ktot >> 6;

    float acc[4][8][4];
    #pragma unroll
    for (int i = 0; i < 4; ++i)
        #pragma unroll
        for (int j = 0; j < 8; ++j)
            #pragma unroll
            for (int q = 0; q < 4; ++q) acc[i][j][q] = 0.f;

    uint32_t sm_offA[4], sm_offB[8];
    const __half* gA[4];
    const __half* gB[8];
    #pragma unroll
    for (int u = 0; u < 4; ++u) {
        int i = tid + u * 256;
        int r = i >> 3, seg = i & 7;
        uint32_t off = (uint32_t)(r * 128 + seg * 16);
        sm_offA[u] = off ^ ((off >> 3) & 0x70);
        gA[u] = A + (size_t)(row0 + r) * lda + (seg << 3);
    }
    #pragma unroll
    for (int u = 0; u < 8; ++u) {
        int i = tid + u * 256;
        int r = i >> 3, seg = i & 7;
        uint32_t off = (uint32_t)(r * 128 + seg * 16);
        sm_offB[u] = off ^ ((off >> 3) & 0x70);
        gB[u] = B + (size_t)(col0 + r) * Ktot + (seg << 3);
    }
    auto load_chunk = [&](int c) {
        const uint32_t s = sb + (uint32_t)((c % BGSTAGE) * BSTG_BYTES);
        const int kof = c << 6;
        #pragma unroll
        for (int u = 0; u < 4; ++u) cp16(s + sm_offA[u], gA[u] + kof);
        #pragma unroll
        for (int u = 0; u < 8; ++u) cp16(s + 16384 + sm_offB[u], gB[u] + kof);
        asm volatile("cp.async.commit_group;");
    };
    #pragma unroll
    for (int c = 0; c < BGSTAGE - 1; ++c) load_chunk(c);

    uint32_t a_base[4], a_swz[4];
    #pragma unroll
    for (int mb = 0; mb < 4; ++mb) {
        int row = wm * 64 + mb * 16 + (lane & 15);
        a_base[mb] = (uint32_t)(row * 128 + ((lane >> 4) << 4));
        a_swz[mb] = (uint32_t)((row & 7) << 4);
    }
    uint32_t b_base[4], b_swz[4];
    #pragma unroll
    for (int nb = 0; nb < 4; ++nb) {
        int row = wn * 64 + nb * 16 + (lane & 7) + ((lane >> 4) << 3);
        b_base[nb] = (uint32_t)(row * 128 + (((lane >> 3) & 1) << 4));
        b_swz[nb] = (uint32_t)((row & 7) << 4);
    }

    for (int c = 0; c < nch; ++c) {
        asm volatile("cp.async.wait_group %0;" :: "n"(BGSTAGE - 2));
        __syncthreads();
        if (c + BGSTAGE - 1 < nch) load_chunk(c + BGSTAGE - 1);
        else asm volatile("cp.async.commit_group;");
        const uint32_t stb = sb + (uint32_t)((c % BGSTAGE) * BSTG_BYTES);
        #pragma unroll
        for (int kk = 0; kk < 4; ++kk) {
            const uint32_t kby = (uint32_t)(kk * 32);
            uint32_t a[4][4];
            #pragma unroll
            for (int mb = 0; mb < 4; ++mb)
                ldsm_x4(a[mb], stb + ((a_base[mb] + kby) ^ a_swz[mb]));
            uint32_t b[4][4];
            #pragma unroll
            for (int nb = 0; nb < 4; ++nb)
                ldsm_x4(b[nb], stb + 16384 + ((b_base[nb] + kby) ^ b_swz[nb]));
            #pragma unroll
            for (int mb = 0; mb < 4; ++mb)
                #pragma unroll
                for (int nb = 0; nb < 4; ++nb) {
                    mma_f16(acc[mb][2 * nb],     a[mb], b[nb][0], b[nb][1]);
                    mma_f16(acc[mb][2 * nb + 1], a[mb], b[nb][2], b[nb][3]);
                }
        }
    }

    const float* bp = bias;
    int cadj = 0;
    if (bias2 && col0 >= halfN) { bp = bias2; cadj = halfN; }
    const int r_base = row0 + wm * 64 + (lane >> 2);
    const int c_base = col0 + wn * 64 + ((lane & 3) << 1);
    #pragma unroll
    for (int mb = 0; mb < 4; ++mb) {
        const int r1 = r_base + mb * 16;
        const int r2 = r1 + 8;
        #pragma unroll
        for (int nt = 0; nt < 8; ++nt) {
            const int col = c_base + nt * 8;
            float bx = bp[col - cadj], by = bp[col + 1 - cadj];
            __half2 t0 = __floats2half2_rn(acc[mb][nt][0] + bx, acc[mb][nt][1] + by);
            __half2 t1 = __floats2half2_rn(acc[mb][nt][2] + bx, acc[mb][nt][3] + by);
            *reinterpret_cast<__half2*>(&C[(size_t)r1 * Nc + col]) = t0;
            *reinterpret_cast<__half2*>(&C[(size_t)r2 * Nc + col]) = t1;
        }
    }
}

// ---------------- fused GATv2 edge kernel: 8 nodes/block, smem table, data prefetch ---
#define EDGE_SMEM (9 * HDc * 4)

__global__ void __launch_bounds__(256)
k_edge(const int* __restrict__ edge_index, const int* __restrict__ edge_attr,
       const float* __restrict__ att_l, const float* __restrict__ bgat_l,
       int loff, __half* __restrict__ packH) {
    extern __shared__ float sm[];
    float* s_att = sm;
    float* s_tab = sm + HDc;
    float* s_xr  = sm + 6 * HDc;
    float* s_lee = sm + 7 * HDc;
    float* s_out = sm + 8 * HDc;

    const int tid = threadIdx.x;
    const int lane = tid & 31;
    const int base = ((tid >> 5) << 8) + (lane << 3);

    const float* tb = g_table + loff;
    #pragma unroll
    for (int u = 0; u < 8; ++u) s_att[tid + u * 256] = att_l[tid + u * 256];
    #pragma unroll
    for (int u = 0; u < 40; ++u) s_tab[tid + u * 256] = tb[tid + u * 256];
    __syncthreads();

    for (int g = 0; g < EGc; ++g) {
        const int n = blockIdx.x * EGc + g;
        const int r0 = g_rowptr[n], r1 = g_rowptr[n + 1];
        const int deg = r1 - r0;
        const float inv = 1.0f / (float)(deg > 1 ? deg : 1);

        float c0 = (float)g_hist[n * NTc + 0];
        float c1 = (float)g_hist[n * NTc + 1];
        float c2 = (float)g_hist[n * NTc + 2];
        float c3 = (float)g_hist[n * NTc + 3];
        float c4 = (float)g_hist[n * NTc + 4];

        {
            int j8 = tid * 8;
            uint4 raw = *reinterpret_cast<const uint4*>(g_xlr + (size_t)n * N2c + HDc + j8);
            __half2 p0 = *reinterpret_cast<__half2*>(&raw.x);
            __half2 p1 = *reinterpret_cast<__half2*>(&raw.y);
            __half2 p2 = *reinterpret_cast<__half2*>(&raw.z);
            __half2 p3 = *reinterpret_cast<__half2*>(&raw.w);
            s_xr[j8 + 0] = __half2float(p0.x); s_xr[j8 + 1] = __half2float(p0.y);
            s_xr[j8 + 2] = __half2float(p1.x); s_xr[j8 + 3] = __half2float(p1.y);
            s_xr[j8 + 4] = __half2float(p2.x); s_xr[j8 + 5] = __half2float(p2.y);
            s_xr[j8 + 6] = __half2float(p3.x); s_xr[j8 + 7] = __half2float(p3.y);
        }
        #pragma unroll
        for (int u = 0; u < 8; ++u) {
            int j = tid + u * 256;
            float v = c0 * s_tab[0 * HDc + j];
            v = fmaf(c1, s_tab[1 * HDc + j], v);
            v = fmaf(c2, s_tab[2 * HDc + j], v);
            v = fmaf(c3, s_tab[3 * HDc + j], v);
            v = fmaf(c4, s_tab[4 * HDc + j], v);
            s_lee[j] = v * inv;
        }
        __syncthreads();

        float m = -1e30f, d = 0.f;
        float acc[8];
        #pragma unroll
        for (int i = 0; i < 8; ++i) acc[i] = 0.f;

        // software pipeline: indices 2 ahead, xl data 1 ahead
        auto fetch_idx = [&](int idx, int& s, int& t) {
            if (idx < r1) { int e = g_eid[idx]; s = edge_index[e]; t = edge_attr[e]; }
            else { s = n; t = -1; }
        };
        int s_c, t_c, s_n, t_n;
        fetch_idx(r0, s_c, t_c);
        uint4 raw_c = *reinterpret_cast<const uint4*>(g_xlr + (size_t)s_c * N2c + base);
        fetch_idx(r0 + 1, s_n, t_n);

        for (int idx = r0; idx <= r1; ++idx) {
            // issue next edge's data load before computing the current one
            uint4 raw_n = *reinterpret_cast<const uint4*>(g_xlr + (size_t)s_n * N2c + base);
            int s_nn, t_nn;
            fetch_idx(idx + 2, s_nn, t_nn);

            __half2 p0 = *reinterpret_cast<__half2*>(&raw_c.x);
            __half2 p1 = *reinterpret_cast<__half2*>(&raw_c.y);
            __half2 p2 = *reinterpret_cast<__half2*>(&raw_c.z);
            __half2 p3 = *reinterpret_cast<__half2*>(&raw_c.w);
            float xlv[8];
            xlv[0] = __half2float(p0.x); xlv[1] = __half2float(p0.y);
            xlv[2] = __half2float(p1.x); xlv[3] = __half2float(p1.y);
            xlv[4] = __half2float(p2.x); xlv[5] = __half2float(p2.y);
            xlv[6] = __half2float(p3.x); xlv[7] = __half2float(p3.y);

            const float* tab = (t_c < 0) ? (s_lee + base) : (s_tab + t_c * HDc + base);
            float part = 0.f;
            #pragma unroll
            for (int i = 0; i < 8; ++i) {
                float z = xlv[i] + s_xr[base + i] + tab[i];
                z = z > 0.f ? z : 0.2f * z;
                part = fmaf(z, s_att[base + i], part);
            }
            #pragma unroll
            for (int o = 16; o > 0; o >>= 1)
                part += __shfl_xor_sync(0xffffffffu, part, o);

            float mn = fmaxf(m, part);
            float sc = __expf(m - mn);
            float p  = __expf(part - mn);
            d = d * sc + p;
            #pragma unroll
            for (int i = 0; i < 8; ++i) acc[i] = fmaf(acc[i], sc, p * xlv[i]);
            m = mn;

            raw_c = raw_n; t_c = t_n;
            s_n = s_nn; t_n = t_nn;
        }

        float invd = 1.0f / d;
        #pragma unroll
        for (int i = 0; i < 8; ++i) s_out[base + i] = acc[i] * invd;
        __syncthreads();

        {
            int c = tid;
            float v = 0.f;
            #pragma unroll
            for (int h = 0; h < HHc; ++h) v += s_out[h * DHc + c];
            v = fmaf(v, 0.125f, bgat_l[c]);
            v = fmaxf(v, 0.f);
            __half hi = __float2half_rn(v);
            __half lo = __float2half_rn(v - __half2float(hi));
            __half* p = packH + (size_t)n * (2 * DHc) + c;
            p[0]   = hi;
            p[DHc] = lo;
        }
        __syncthreads();
    }
}

// ---------------- host orchestration ----------------
extern "C" void kernel_launch(void* const* d_in, const int* in_sizes, int n_in,
                              void* d_out, int out_size) {
    const float* x         = (const float*)d_in[0];
    const int*   edge_index= (const int*)  d_in[1];
    const int*   edge_attr = (const int*)  d_in[2];
    const int*   node_types= (const int*)  d_in[3];
    const float* W_in      = (const float*)d_in[4];
    const float* b_in      = (const float*)d_in[5];
    const float* node_emb  = (const float*)d_in[6];
    const float* edge_emb  = (const float*)d_in[7];
    const float* Wl        = (const float*)d_in[8];
    const float* bl        = (const float*)d_in[9];
    const float* Wr        = (const float*)d_in[10];
    const float* br        = (const float*)d_in[11];
    const float* We        = (const float*)d_in[12];
    const float* att       = (const float*)d_in[13];
    const float* b_gat     = (const float*)d_in[14];
    const float* W_out     = (const float*)d_in[15];
    const float* b_out     = (const float*)d_in[16];
    float* out = (float*)d_out;

    __half* xlr;    cudaGetSymbolAddress((void**)&xlr, g_xlr);
    __half* Apk;    cudaGetSymbolAddress((void**)&Apk, g_Apack);
    __half* Hpk;    cudaGetSymbolAddress((void**)&Hpk, g_hpack);
    __half* Bpk;    cudaGetSymbolAddress((void**)&Bpk, g_Bpack);

    cudaFuncSetAttribute(k_gemm_mma, cudaFuncAttributeMaxDynamicSharedMemorySize, GEMM_SMEM);
    cudaFuncSetAttribute(k_gemm_big, cudaFuncAttributeMaxDynamicSharedMemorySize, BGEMM_SMEM);
    cudaFuncSetAttribute(k_edge, cudaFuncAttributeMaxDynamicSharedMemorySize, EDGE_SMEM);

    // 1: pack everything
    k_pack_all<<<Nn + 256 + 3072 + 64 + 120, 256>>>(x, W_in, Wl, Wr, W_out,
                                                    edge_emb, We, Apk, Bpk);
    // 2: CSR zero
    k_zero<<<(Nn * NTc + 255) / 256, 256>>>();
    // 3: input projection -> packed h0 (fp16x2, K=2048)
    k_gemm_mma<<<dim3(2, 64), 256, GEMM_SMEM>>>(
        Apk, Bpk + OFF_WIN, b_in, nullptr, 2 * DINc, DHc, node_emb, node_types, Hpk);
    // 4: merged xl|xr GEMM layer 0 (single-pass fp16, K=256)  <- ncu capture slot
    k_gemm_big<<<dim3(N2c / 256, 64), 256, BGEMM_SMEM>>>(
        Hpk, 2 * DHc, Bpk + OFF_WLR(0), bl, br, HDc, xlr, DHc, N2c);
    // 5-8: finish CSR
    k_count<<<(Ee + 255) / 256, 256>>>(edge_index, edge_attr);
    k_scan<<<1, 256>>>();
    k_fill<<<(Ee + 255) / 256, 256>>>(edge_index);
    k_sort<<<(Nn + 255) / 256, 256>>>();

    for (int l = 0; l < LLc; ++l) {
        if (l > 0) {
            k_gemm_big<<<dim3(N2c / 256, 64), 256, BGEMM_SMEM>>>(
                Hpk, 2 * DHc, Bpk + OFF_WLR(l), bl + (size_t)l * HDc, br + (size_t)l * HDc,
                HDc, xlr, DHc, N2c);
        }
        k_edge<<<Nn / EGc, 256, EDGE_SMEM>>>(edge_index, edge_attr,
                                             att + (size_t)l * HHc * DHc,
                                             b_gat + (size_t)l * DHc,
                                             l * NTc * HDc, Hpk);
    }

    // output projection -> d_out fp32 (fp16x2, K=512)
    k_gemm_mma<<<dim3(2, 64), 256, GEMM_SMEM>>>(
        Hpk, Bpk + OFF_WOUT, b_out, out, 2 * DHc, DHc, nullptr, nullptr, nullptr);

    (void)in_sizes; (void)n_in; (void)out_size;
}

// round 11
// speedup vs baseline: 2.3005x; 1.0028x over previous
#include <cuda_runtime.h>
#include <cuda_fp16.h>
#include <math.h>
#include <stdint.h>

// Problem constants
#define Nn   8192
#define Ee   32768
#define DINc 1024
#define DHc  256
#define HHc  8
#define LLc  3
#define HDc  2048   // H*DH
#define NTc  5
#define N2c  4096   // merged Wl|Wr output width
#define EGc  8      // nodes per edge-kernel block

// ---------------- device scratch ----------------
__device__ __half g_xlr[(size_t)Nn * N2c];         // merged xl|xr, fp16 (L2-resident)
__device__ float g_table[LLc * NTc * HDc];
__device__ int   g_deg[Nn];
__device__ int   g_hist[Nn * NTc];
__device__ int   g_rowptr[Nn + 1];
__device__ int   g_woff[Nn];
__device__ int   g_eid[Ee];

// Apack: [Ah] single (K=1024). hpack: [Ah|Al] fp16x2 (2K=512).
// Bpack: W_in single (K=1024); Wl/Wr single (K=256); W_out dup (2K=512).
__device__ __half g_Apack[(size_t)Nn * DINc];
__device__ __half g_hpack[(size_t)Nn * 2 * DHc];
__device__ __half g_Bpack[4000000];

#define OFF_WIN  0
#define SZ_WIN   (DHc * DINc)                     // 262144
#define SZ_L     ((size_t)N2c * DHc)              // 1048576
#define OFF_WLR(l) (SZ_WIN + (size_t)(l) * SZ_L)
#define OFF_WOUT (SZ_WIN + (size_t)3 * SZ_L)

// ---------------- PTX helpers ----------------
__device__ __forceinline__ uint32_t smem_u32(const void* p) {
    uint32_t a;
    asm("{ .reg .u64 t; cvta.to.shared.u64 t, %1; cvt.u32.u64 %0, t; }" : "=r"(a) : "l"(p));
    return a;
}
__device__ __forceinline__ void cp16(uint32_t d, const void* g) {
    asm volatile("cp.async.cg.shared.global [%0], [%1], 16;" :: "r"(d), "l"(g));
}
__device__ __forceinline__ void ldsm_x4(uint32_t* r, uint32_t addr) {
    asm volatile("ldmatrix.sync.aligned.m8n8.x4.shared.b16 {%0,%1,%2,%3}, [%4];"
                 : "=r"(r[0]), "=r"(r[1]), "=r"(r[2]), "=r"(r[3]) : "r"(addr));
}
__device__ __forceinline__ void mma_f16(float* c, const uint32_t* a, uint32_t b0, uint32_t b1) {
    asm volatile(
        "mma.sync.aligned.m16n8k16.row.col.f32.f16.f16.f32 "
        "{%0,%1,%2,%3}, {%4,%5,%6,%7}, {%8,%9}, {%0,%1,%2,%3};"
        : "+f"(c[0]), "+f"(c[1]), "+f"(c[2]), "+f"(c[3])
        : "r"(a[0]), "r"(a[1]), "r"(a[2]), "r"(a[3]), "r"(b0), "r"(b1));
}

// ---------------- CSR build ----------------
__global__ void k_zero() {
    int i = blockIdx.x * 256 + threadIdx.x;
    if (i < Nn) g_deg[i] = 0;
    if (i < Nn * NTc) g_hist[i] = 0;
}
__global__ void k_count(const int* __restrict__ ei, const int* __restrict__ ea) {
    int e = blockIdx.x * 256 + threadIdx.x;
    if (e < Ee) {
        int dst = ei[Ee + e];
        atomicAdd(&g_deg[dst], 1);
        atomicAdd(&g_hist[dst * NTc + ea[e]], 1);
    }
}
__global__ void k_scan() {
    __shared__ int part[256];
    int tid = threadIdx.x;
    int base = tid * 32;
    int s = 0;
    for (int i = 0; i < 32; ++i) s += g_deg[base + i];
    part[tid] = s;
    __syncthreads();
    for (int off = 1; off < 256; off <<= 1) {
        int v = (tid >= off) ? part[tid - off] : 0;
        __syncthreads();
        part[tid] += v;
        __syncthreads();
    }
    int run = (tid == 0) ? 0 : part[tid - 1];
    for (int i = 0; i < 32; ++i) {
        int n = base + i;
        g_rowptr[n] = run;
        g_woff[n] = run;
        run += g_deg[n];
    }
    if (tid == 255) g_rowptr[Nn] = run;
}
__global__ void k_fill(const int* __restrict__ ei) {
    int e = blockIdx.x * 256 + threadIdx.x;
    if (e < Ee) {
        int dst = ei[Ee + e];
        int pos = atomicAdd(&g_woff[dst], 1);
        g_eid[pos] = e;
    }
}
__global__ void k_sort() {
    int n = blockIdx.x * 256 + threadIdx.x;
    if (n < Nn) {
        int r0 = g_rowptr[n], r1 = g_rowptr[n + 1];
        for (int i = r0 + 1; i < r1; ++i) {
            int v = g_eid[i];
            int j = i - 1;
            while (j >= r0 && g_eid[j] > v) { g_eid[j + 1] = g_eid[j]; --j; }
            g_eid[j + 1] = v;
        }
    }
}

// ---------------- fused packing: x, all weights, all tables ----------------
__global__ void __launch_bounds__(256)
k_pack_all(const float* __restrict__ x,
           const float* __restrict__ W_in,
           const float* __restrict__ Wl, const float* __restrict__ Wr,
           const float* __restrict__ W_out,
           const float* __restrict__ edge_emb, const float* __restrict__ We,
           __half* __restrict__ Apk, __half* __restrict__ Bpk) {
    const int bid = blockIdx.x;
    const int tid = threadIdx.x;

    if (bid < Nn) {
        // pack x row -> [Ah] single copy
        const float4 v = *reinterpret_cast<const float4*>(x + (size_t)bid * DINc + tid * 4);
        __half2 hp0 = {__float2half_rn(v.x), __float2half_rn(v.y)};
        __half2 hp1 = {__float2half_rn(v.z), __float2half_rn(v.w)};
        __half* p = Apk + (size_t)bid * DINc + tid * 4;
        reinterpret_cast<__half2*>(p)[0] = hp0;
        reinterpret_cast<__half2*>(p)[1] = hp1;
        return;
    }
    if (bid < Nn + 256 + 3072 + 64) {
        const float* W; __half* P; int K, N, nb, kb;
        bool dup;
        int id = bid - Nn;
        if (id < 256) {
            W = W_in; P = Bpk + OFF_WIN; K = DINc; N = DHc; dup = false;
            nb = id & 7; kb = id >> 3;
        } else if (id < 256 + 3072) {
            int id2 = id - 256;
            int mat = id2 >> 9;
            int t = id2 & 511;
            int l = mat >> 1, side = mat & 1;
            W = (side == 0 ? Wl : Wr) + (size_t)l * DHc * HDc;
            P = Bpk + OFF_WLR(l) + (size_t)side * HDc * DHc;
            K = DHc; N = HDc; dup = false;
            nb = t & 63; kb = t >> 6;
        } else {
            int id2 = id - 256 - 3072;
            W = W_out; P = Bpk + OFF_WOUT; K = DHc; N = DHc; dup = true;
            nb = id2 & 7; kb = id2 >> 3;
        }
        __shared__ float tbuf[32][33];
        int tx = tid & 31, ty = tid >> 5;
        #pragma unroll
        for (int i = 0; i < 32; i += 8)
            tbuf[ty + i][tx] = W[(size_t)(kb * 32 + ty + i) * N + nb * 32 + tx];
        __syncthreads();
        const int stride = dup ? 2 * K : K;
        #pragma unroll
        for (int i = 0; i < 32; i += 8) {
            int n = nb * 32 + ty + i;
            int k = kb * 32 + tx;
            __half hi = __float2half_rn(tbuf[tx][ty + i]);
            P[(size_t)n * stride + k] = hi;
            if (dup) P[(size_t)n * stride + K + k] = hi;
        }
        return;
    }
    {
        int id = bid - (Nn + 256 + 3072 + 64);
        int lt = id >> 3;
        int jb = id & 7;
        int l = lt / NTc, t = lt % NTc;
        int j = jb * 256 + tid;
        const float* w = We + (size_t)l * DHc * HDc + j;
        const float* e = edge_emb + t * DHc;
        float s = 0.f;
        #pragma unroll 4
        for (int k = 0; k < DHc; ++k) s = fmaf(e[k], w[(size_t)k * HDc], s);
        g_table[(size_t)l * NTc * HDc + t * HDc + j] = s;
    }
}

// ---------------- GEMM kernel 1 (proj): CTA 128x128, warp 32x64, 3-stage, 2 CTA/SM ----
#define GSTAGE 3
#define STG_BYTES 32768
#define GEMM_SMEM (GSTAGE * STG_BYTES)

__global__ void __launch_bounds__(256, 2)
k_gemm_mma(const __half* __restrict__ A, int lda, const __half* __restrict__ B,
           const float* __restrict__ bias, float* __restrict__ C, int Ktot, int Nc,
           const float* __restrict__ emb, const int* __restrict__ types,
           __half* __restrict__ packA) {
    extern __shared__ __align__(1024) char smem[];
    const uint32_t sb = smem_u32(smem);
    const int tid = threadIdx.x;
    const int lane = tid & 31, w = tid >> 5;
    const int wm = w & 3, wn = w >> 2;
    const int row0 = blockIdx.y * 128;
    const int col0 = blockIdx.x * 128;
    const int nch = Ktot >> 6;

    float acc[2][8][4];
    #pragma unroll
    for (int i = 0; i < 2; ++i)
        #pragma unroll
        for (int j = 0; j < 8; ++j)
            #pragma unroll
            for (int q = 0; q < 4; ++q) acc[i][j][q] = 0.f;

    uint32_t sm_off[4];
    const __half* gA[4];
    const __half* gB[4];
    #pragma unroll
    for (int u = 0; u < 4; ++u) {
        int i = tid + u * 256;
        int r = i >> 3, seg = i & 7;
        uint32_t off = (uint32_t)(r * 128 + seg * 16);
        sm_off[u] = off ^ ((off >> 3) & 0x70);
        gA[u] = A + (size_t)(row0 + r) * lda + (seg << 3);
        gB[u] = B + (size_t)(col0 + r) * Ktot + (seg << 3);
    }
    auto load_chunk = [&](int c) {
        const uint32_t s = sb + (uint32_t)((c % GSTAGE) * STG_BYTES);
        const int kof = c << 6;
        #pragma unroll
        for (int u = 0; u < 4; ++u) cp16(s + sm_off[u], gA[u] + kof);
        #pragma unroll
        for (int u = 0; u < 4; ++u) cp16(s + 16384 + sm_off[u], gB[u] + kof);
        asm volatile("cp.async.commit_group;");
    };
    #pragma unroll
    for (int c = 0; c < GSTAGE - 1; ++c) load_chunk(c);

    uint32_t a_base[2], a_swz[2];
    #pragma unroll
    for (int mb = 0; mb < 2; ++mb) {
        int row = wm * 32 + mb * 16 + (lane & 15);
        a_base[mb] = (uint32_t)(row * 128 + ((lane >> 4) << 4));
        a_swz[mb] = (uint32_t)((row & 7) << 4);
    }
    uint32_t b_base[4], b_swz[4];
    #pragma unroll
    for (int nb = 0; nb < 4; ++nb) {
        int row = wn * 64 + nb * 16 + (lane & 7) + ((lane >> 4) << 3);
        b_base[nb] = (uint32_t)(row * 128 + (((lane >> 3) & 1) << 4));
        b_swz[nb] = (uint32_t)((row & 7) << 4);
    }

    for (int c = 0; c < nch; ++c) {
        asm volatile("cp.async.wait_group %0;" :: "n"(GSTAGE - 2));
        __syncthreads();
        if (c + GSTAGE - 1 < nch) load_chunk(c + GSTAGE - 1);
        else asm volatile("cp.async.commit_group;");
        const uint32_t stb = sb + (uint32_t)((c % GSTAGE) * STG_BYTES);
        #pragma unroll
        for (int kk = 0; kk < 4; ++kk) {
            const uint32_t kby = (uint32_t)(kk * 32);
            uint32_t a[2][4];
            #pragma unroll
            for (int mb = 0; mb < 2; ++mb)
                ldsm_x4(a[mb], stb + ((a_base[mb] + kby) ^ a_swz[mb]));
            uint32_t b[4][4];
            #pragma unroll
            for (int nb = 0; nb < 4; ++nb)
                ldsm_x4(b[nb], stb + 16384 + ((b_base[nb] + kby) ^ b_swz[nb]));
            #pragma unroll
            for (int mb = 0; mb < 2; ++mb)
                #pragma unroll
                for (int nb = 0; nb < 4; ++nb) {
                    mma_f16(acc[mb][2 * nb],     a[mb], b[nb][0], b[nb][1]);
                    mma_f16(acc[mb][2 * nb + 1], a[mb], b[nb][2], b[nb][3]);
                }
        }
    }

    const int r_base = row0 + wm * 32 + (lane >> 2);
    const int c_base = col0 + wn * 64 + ((lane & 3) << 1);
    const int K2 = 2 * Nc;
    #pragma unroll
    for (int mb = 0; mb < 2; ++mb) {
        const int r1 = r_base + mb * 16;
        const int r2 = r1 + 8;
        #pragma unroll
        for (int nt = 0; nt < 8; ++nt) {
            const int col = c_base + nt * 8;
            float bx = bias[col], by = bias[col + 1];
            float e1x = 0.f, e1y = 0.f, e2x = 0.f, e2y = 0.f;
            if (emb) {
                const float* em1 = emb + (size_t)types[r1] * Nc + col;
                const float* em2 = emb + (size_t)types[r2] * Nc + col;
                e1x = em1[0]; e1y = em1[1]; e2x = em2[0]; e2y = em2[1];
            }
            float v00 = acc[mb][nt][0] + bx + e1x;
            float v01 = acc[mb][nt][1] + by + e1y;
            float v10 = acc[mb][nt][2] + bx + e2x;
            float v11 = acc[mb][nt][3] + by + e2y;
            if (C) {
                float2 t0 = {v00, v01}, t1 = {v10, v11};
                *reinterpret_cast<float2*>(&C[(size_t)r1 * Nc + col]) = t0;
                *reinterpret_cast<float2*>(&C[(size_t)r2 * Nc + col]) = t1;
            }
            if (packA) {
                __half h00 = __float2half_rn(v00);
                __half h01 = __float2half_rn(v01);
                __half h10 = __float2half_rn(v10);
                __half h11 = __float2half_rn(v11);
                __half2 hp1 = {h00, h01};
                __half2 hp2 = {h10, h11};
                __half2 lp1 = {__float2half_rn(v00 - __half2float(h00)),
                               __float2half_rn(v01 - __half2float(h01))};
                __half2 lp2 = {__float2half_rn(v10 - __half2float(h10)),
                               __float2half_rn(v11 - __half2float(h11))};
                __half* p1 = packA + (size_t)r1 * K2 + col;
                __half* p2 = packA + (size_t)r2 * K2 + col;
                *reinterpret_cast<__half2*>(p1)      = hp1;
                *reinterpret_cast<__half2*>(p1 + Nc) = lp1;
                *reinterpret_cast<__half2*>(p2)      = hp2;
                *reinterpret_cast<__half2*>(p2 + Nc) = lp2;
            }
        }
    }
}

// ---------------- GEMM kernel 2 (merged xl|xr): CTA 128x256, warp 64x64, 4-stage ----
#define BGSTAGE 4
#define BSTG_BYTES 49152
#define BGEMM_SMEM (BGSTAGE * BSTG_BYTES)

__global__ void __launch_bounds__(256, 1)
k_gemm_big(const __half* __restrict__ A, int lda, const __half* __restrict__ B,
           const float* __restrict__ bias, const float* __restrict__ bias2, int halfN,
           __half* __restrict__ C, int Ktot, int Nc) {
    extern __shared__ __align__(1024) char smem[];
    const uint32_t sb = smem_u32(smem);
    const int tid = threadIdx.x;
    const int lane = tid & 31, w = tid >> 5;
    const int wm = w & 1, wn = w >> 1;
    const int row0 = blockIdx.y * 128;
    const int col0 = blockIdx.x * 256;
    const int nch = Ktot >> 6;

    float acc[4][8][4];
    #pragma unroll
    for (int i = 0; i < 4; ++i)
        #pragma unroll
        for (int j = 0; j < 8; ++j)
            #pragma unroll
            for (int q = 0; q < 4; ++q) acc[i][j][q] = 0.f;

    uint32_t sm_offA[4], sm_offB[8];
    const __half* gA[4];
    const __half* gB[8];
    #pragma unroll
    for (int u = 0; u < 4; ++u) {
        int i = tid + u * 256;
        int r = i >> 3, seg = i & 7;
        uint32_t off = (uint32_t)(r * 128 + seg * 16);
        sm_offA[u] = off ^ ((off >> 3) & 0x70);
        gA[u] = A + (size_t)(row0 + r) * lda + (seg << 3);
    }
    #pragma unroll
    for (int u = 0; u < 8; ++u) {
        int i = tid + u * 256;
        int r = i >> 3, seg = i & 7;
        uint32_t off = (uint32_t)(r * 128 + seg * 16);
        sm_offB[u] = off ^ ((off >> 3) & 0x70);
        gB[u] = B + (size_t)(col0 + r) * Ktot + (seg << 3);
    }
    auto load_chunk = [&](int c) {
        const uint32_t s = sb + (uint32_t)((c % BGSTAGE) * BSTG_BYTES);
        const int kof = c << 6;
        #pragma unroll
        for (int u = 0; u < 4; ++u) cp16(s + sm_offA[u], gA[u] + kof);
        #pragma unroll
        for (int u = 0; u < 8; ++u) cp16(s + 16384 + sm_offB[u], gB[u] + kof);
        asm volatile("cp.async.commit_group;");
    };
    #pragma unroll
    for (int c = 0; c < BGSTAGE - 1; ++c) load_chunk(c);

    uint32_t a_base[4], a_swz[4];
    #pragma unroll
    for (int mb = 0; mb < 4; ++mb) {
        int row = wm * 64 + mb * 16 + (lane & 15);
        a_base[mb] = (uint32_t)(row * 128 + ((lane >> 4) << 4));
        a_swz[mb] = (uint32_t)((row & 7) << 4);
    }
    uint32_t b_base[4], b_swz[4];
    #pragma unroll
    for (int nb = 0; nb < 4; ++nb) {
        int row = wn * 64 + nb * 16 + (lane & 7) + ((lane >> 4) << 3);
        b_base[nb] = (uint32_t)(row * 128 + (((lane >> 3) & 1) << 4));
        b_swz[nb] = (uint32_t)((row & 7) << 4);
    }

    for (int c = 0; c < nch; ++c) {
        asm volatile("cp.async.wait_group %0;" :: "n"(BGSTAGE - 2));
        __syncthreads();
        if (c + BGSTAGE - 1 < nch) load_chunk(c + BGSTAGE - 1);
        else asm volatile("cp.async.commit_group;");
        const uint32_t stb = sb + (uint32_t)((c % BGSTAGE) * BSTG_BYTES);
        #pragma unroll
        for (int kk = 0; kk < 4; ++kk) {
            const uint32_t kby = (uint32_t)(kk * 32);
            uint32_t a[4][4];
            #pragma unroll
            for (int mb = 0; mb < 4; ++mb)
                ldsm_x4(a[mb], stb + ((a_base[mb] + kby) ^ a_swz[mb]));
            uint32_t b[4][4];
            #pragma unroll
            for (int nb = 0; nb < 4; ++nb)
                ldsm_x4(b[nb], stb + 16384 + ((b_base[nb] + kby) ^ b_swz[nb]));
            #pragma unroll
            for (int mb = 0; mb < 4; ++mb)
                #pragma unroll
                for (int nb = 0; nb < 4; ++nb) {
                    mma_f16(acc[mb][2 * nb],     a[mb], b[nb][0], b[nb][1]);
                    mma_f16(acc[mb][2 * nb + 1], a[mb], b[nb][2], b[nb][3]);
                }
        }
    }

    const float* bp = bias;
    int cadj = 0;
    if (bias2 && col0 >= halfN) { bp = bias2; cadj = halfN; }
    const int r_base = row0 + wm * 64 + (lane >> 2);
    const int c_base = col0 + wn * 64 + ((lane & 3) << 1);
    #pragma unroll
    for (int mb = 0; mb < 4; ++mb) {
        const int r1 = r_base + mb * 16;
        const int r2 = r1 + 8;
        #pragma unroll
        for (int nt = 0; nt < 8; ++nt) {
            const int col = c_base + nt * 8;
            float bx = bp[col - cadj], by = bp[col + 1 - cadj];
            __half2 t0 = __floats2half2_rn(acc[mb][nt][0] + bx, acc[mb][nt][1] + by);
            __half2 t1 = __floats2half2_rn(acc[mb][nt][2] + bx, acc[mb][nt][3] + by);
            *reinterpret_cast<__half2*>(&C[(size_t)r1 * Nc + col]) = t0;
            *reinterpret_cast<__half2*>(&C[(size_t)r2 * Nc + col]) = t1;
        }
    }
}

// ---------------- fused GATv2 edge kernel: 8 nodes/block, pairwise-unrolled softmax ---
#define EDGE_SMEM (9 * HDc * 4)

__device__ __forceinline__ void h8_to_f(const uint4& raw, float* x) {
    __half2 p0 = *reinterpret_cast<const __half2*>(&raw.x);
    __half2 p1 = *reinterpret_cast<const __half2*>(&raw.y);
    __half2 p2 = *reinterpret_cast<const __half2*>(&raw.z);
    __half2 p3 = *reinterpret_cast<const __half2*>(&raw.w);
    x[0] = __half2float(p0.x); x[1] = __half2float(p0.y);
    x[2] = __half2float(p1.x); x[3] = __half2float(p1.y);
    x[4] = __half2float(p2.x); x[5] = __half2float(p2.y);
    x[6] = __half2float(p3.x); x[7] = __half2float(p3.y);
}

__global__ void __launch_bounds__(256)
k_edge(const int* __restrict__ edge_index, const int* __restrict__ edge_attr,
       const float* __restrict__ att_l, const float* __restrict__ bgat_l,
       int loff, __half* __restrict__ packH) {
    extern __shared__ float sm[];
    float* s_att = sm;
    float* s_tab = sm + HDc;
    float* s_xr  = sm + 6 * HDc;
    float* s_lee = sm + 7 * HDc;
    float* s_out = sm + 8 * HDc;

    const int tid = threadIdx.x;
    const int lane = tid & 31;
    const int base = ((tid >> 5) << 8) + (lane << 3);

    const float* tb = g_table + loff;
    #pragma unroll
    for (int u = 0; u < 8; ++u) s_att[tid + u * 256] = att_l[tid + u * 256];
    #pragma unroll
    for (int u = 0; u < 40; ++u) s_tab[tid + u * 256] = tb[tid + u * 256];
    __syncthreads();

    for (int g = 0; g < EGc; ++g) {
        const int n = blockIdx.x * EGc + g;
        const int r0 = g_rowptr[n], r1 = g_rowptr[n + 1];
        const int deg = r1 - r0;
        const float inv = 1.0f / (float)(deg > 1 ? deg : 1);

        float c0 = (float)g_hist[n * NTc + 0];
        float c1 = (float)g_hist[n * NTc + 1];
        float c2 = (float)g_hist[n * NTc + 2];
        float c3 = (float)g_hist[n * NTc + 3];
        float c4 = (float)g_hist[n * NTc + 4];

        {
            int j8 = tid * 8;
            uint4 raw = *reinterpret_cast<const uint4*>(g_xlr + (size_t)n * N2c + HDc + j8);
            h8_to_f(raw, s_xr + j8);
        }
        #pragma unroll
        for (int u = 0; u < 8; ++u) {
            int j = tid + u * 256;
            float v = c0 * s_tab[0 * HDc + j];
            v = fmaf(c1, s_tab[1 * HDc + j], v);
            v = fmaf(c2, s_tab[2 * HDc + j], v);
            v = fmaf(c3, s_tab[3 * HDc + j], v);
            v = fmaf(c4, s_tab[4 * HDc + j], v);
            s_lee[j] = v * inv;
        }
        __syncthreads();

        float m = -1e30f, d = 0.f;
        float acc[8];
        #pragma unroll
        for (int i = 0; i < 8; ++i) acc[i] = 0.f;

        auto fetch_idx = [&](int idx, int& s, int& t) {
            if (idx < r1) { int e = g_eid[idx]; s = edge_index[e]; t = edge_attr[e]; }
            else { s = n; t = -1; }
        };

        // logit for edge (data in raw, type t) from this warp's head slice
        auto logit = [&](const float* xlv, int t) -> float {
            const float* tab = (t < 0) ? (s_lee + base) : (s_tab + t * HDc + base);
            float part = 0.f;
            #pragma unroll
            for (int i = 0; i < 8; ++i) {
                float z = xlv[i] + s_xr[base + i] + tab[i];
                z = z > 0.f ? z : 0.2f * z;
                part = fmaf(z, s_att[base + i], part);
            }
            return part;
        };
        auto update = [&](float part, const float* xlv) {
            float mn = fmaxf(m, part);
            float sc = __expf(m - mn);
            float p  = __expf(part - mn);
            d = d * sc + p;
            #pragma unroll
            for (int i = 0; i < 8; ++i) acc[i] = fmaf(acc[i], sc, p * xlv[i]);
            m = mn;
        };

        // pair-wise loop over [r0, r1] inclusive (self-loop at r1)
        int s0, t0, s1, t1, s2, t2, s3, t3;
        fetch_idx(r0, s0, t0);
        fetch_idx(r0 + 1, s1, t1);
        uint4 raw0 = *reinterpret_cast<const uint4*>(g_xlr + (size_t)s0 * N2c + base);
        uint4 raw1 = *reinterpret_cast<const uint4*>(g_xlr + (size_t)s1 * N2c + base);
        fetch_idx(r0 + 2, s2, t2);
        fetch_idx(r0 + 3, s3, t3);

        int idx = r0;
        for (; idx + 1 <= r1; idx += 2) {
            // prefetch next pair's data while computing current
            uint4 n0 = *reinterpret_cast<const uint4*>(g_xlr + (size_t)s2 * N2c + base);
            uint4 n1 = *reinterpret_cast<const uint4*>(g_xlr + (size_t)s3 * N2c + base);
            int s4, t4, s5, t5;
            fetch_idx(idx + 4, s4, t4);
            fetch_idx(idx + 5, s5, t5);

            float x0[8], x1[8];
            h8_to_f(raw0, x0);
            h8_to_f(raw1, x1);
            float p0 = logit(x0, t0);
            float p1 = logit(x1, t1);
            #pragma unroll
            for (int o = 16; o > 0; o >>= 1) {
                p0 += __shfl_xor_sync(0xffffffffu, p0, o);
                p1 += __shfl_xor_sync(0xffffffffu, p1, o);
            }
            update(p0, x0);
            update(p1, x1);

            raw0 = n0; raw1 = n1; t0 = t2; t1 = t3;
            s2 = s4; t2 = t4; s3 = s5; t3 = t5;
        }
        if (idx <= r1) {   // odd remainder (data already in raw0, type t0)
            float x0[8];
            h8_to_f(raw0, x0);
            float p0 = logit(x0, t0);
            #pragma unroll
            for (int o = 16; o > 0; o >>= 1)
                p0 += __shfl_xor_sync(0xffffffffu, p0, o);
            update(p0, x0);
        }

        float invd = 1.0f / d;
        #pragma unroll
        for (int i = 0; i < 8; ++i) s_out[base + i] = acc[i] * invd;
        __syncthreads();

        {
            int c = tid;
            float v = 0.f;
            #pragma unroll
            for (int h = 0; h < HHc; ++h) v += s_out[h * DHc + c];
            v = fmaf(v, 0.125f, bgat_l[c]);
            v = fmaxf(v, 0.f);
            __half hi = __float2half_rn(v);
            __half lo = __float2half_rn(v - __half2float(hi));
            __half* p = packH + (size_t)n * (2 * DHc) + c;
            p[0]   = hi;
            p[DHc] = lo;
        }
        __syncthreads();
    }
}

// ---------------- host orchestration ----------------
extern "C" void kernel_launch(void* const* d_in, const int* in_sizes, int n_in,
                              void* d_out, int out_size) {
    const float* x         = (const float*)d_in[0];
    const int*   edge_index= (const int*)  d_in[1];
    const int*   edge_attr = (const int*)  d_in[2];
    const int*   node_types= (const int*)  d_in[3];
    const float* W_in      = (const float*)d_in[4];
    const float* b_in      = (const float*)d_in[5];
    const float* node_emb  = (const float*)d_in[6];
    const float* edge_emb  = (const float*)d_in[7];
    const float* Wl        = (const float*)d_in[8];
    const float* bl        = (const float*)d_in[9];
    const float* Wr        = (const float*)d_in[10];
    const float* br        = (const float*)d_in[11];
    const float* We        = (const float*)d_in[12];
    const float* att       = (const float*)d_in[13];
    const float* b_gat     = (const float*)d_in[14];
    const float* W_out     = (const float*)d_in[15];
    const float* b_out     = (const float*)d_in[16];
    float* out = (float*)d_out;

    __half* xlr;    cudaGetSymbolAddress((void**)&xlr, g_xlr);
    __half* Apk;    cudaGetSymbolAddress((void**)&Apk, g_Apack);
    __half* Hpk;    cudaGetSymbolAddress((void**)&Hpk, g_hpack);
    __half* Bpk;    cudaGetSymbolAddress((void**)&Bpk, g_Bpack);

    cudaFuncSetAttribute(k_gemm_mma, cudaFuncAttributeMaxDynamicSharedMemorySize, GEMM_SMEM);
    cudaFuncSetAttribute(k_gemm_big, cudaFuncAttributeMaxDynamicSharedMemorySize, BGEMM_SMEM);
    cudaFuncSetAttribute(k_edge, cudaFuncAttributeMaxDynamicSharedMemorySize, EDGE_SMEM);

    // 1: pack everything
    k_pack_all<<<Nn + 256 + 3072 + 64 + 120, 256>>>(x, W_in, Wl, Wr, W_out,
                                                    edge_emb, We, Apk, Bpk);
    // 2: CSR zero
    k_zero<<<(Nn * NTc + 255) / 256, 256>>>();
    // 3: input projection -> packed h0 (single-pass fp16, K=1024)
    k_gemm_mma<<<dim3(2, 64), 256, GEMM_SMEM>>>(
        Apk, DINc, Bpk + OFF_WIN, b_in, nullptr, DINc, DHc, node_emb, node_types, Hpk);
    // 4: merged xl|xr GEMM layer 0 (single-pass fp16, K=256)  <- ncu capture slot
    k_gemm_big<<<dim3(N2c / 256, 64), 256, BGEMM_SMEM>>>(
        Hpk, 2 * DHc, Bpk + OFF_WLR(0), bl, br, HDc, xlr, DHc, N2c);
    // 5-8: finish CSR
    k_count<<<(Ee + 255) / 256, 256>>>(edge_index, edge_attr);
    k_scan<<<1, 256>>>();
    k_fill<<<(Ee + 255) / 256, 256>>>(edge_index);
    k_sort<<<(Nn + 255) / 256, 256>>>();

    for (int l = 0; l < LLc; ++l) {
        if (l > 0) {
            k_gemm_big<<<dim3(N2c / 256, 64), 256, BGEMM_SMEM>>>(
                Hpk, 2 * DHc, Bpk + OFF_WLR(l), bl + (size_t)l * HDc, br + (size_t)l * HDc,
                HDc, xlr, DHc, N2c);
        }
        k_edge<<<Nn / EGc, 256, EDGE_SMEM>>>(edge_index, edge_attr,
                                             att + (size_t)l * HHc * DHc,
                                             b_gat + (size_t)l * DHc,
                                             l * NTc * HDc, Hpk);
    }

    // output projection -> d_out fp32 (fp16x2 correction, K=512)
    k_gemm_mma<<<dim3(2, 64), 256, GEMM_SMEM>>>(
        Hpk, 2 * DHc, Bpk + OFF_WOUT, b_out, out, 2 * DHc, DHc, nullptr, nullptr, nullptr);

    (void)in_sizes; (void)n_in; (void)out_size;
}